// round 8
// baseline (speedup 1.0000x reference)
#include <cuda_runtime.h>
#include <cuda_fp16.h>
#include <cstdint>
#include <math.h>

constexpr int CB = 2, CS = 2048, CE = 512, CH = 8, CBS = CB * CS;

// ---------------- scratch (device globals; allocation-free) ----------------
__device__ __align__(128) float g_scores[(size_t)CB * CH * CS * CS];  // 268 MB
__device__ __align__(128) __half g_xh[CBS * CE], g_xl[CBS * CE];
__device__ __align__(128) __half g_qh[CBS * CE], g_ql[CBS * CE];
__device__ __align__(128) __half g_kh[CBS * CE];                       // B-only: hi
// stacked [x ; v] per batch (B-only: hi): [b][0..2047]=x, [b][2048..4095]=v
__device__ __align__(128) __half g_xvh[(size_t)CB * 2 * CS * CE];
__device__ __align__(128) __half g_t1h[CBS * CE], g_t1l[CBS * CE];
__device__ __align__(128) __half g_t2h[CBS * CE], g_t2l[CBS * CE];
// combined A-operand weights [b][i][0..2047]=wk, [b][i][2048..4095]=wm (hi+lo)
__device__ __align__(128) __half g_wh[(size_t)CB * CS * 2 * CS], g_wl[(size_t)CB * CS * 2 * CS];
__device__ __align__(128) __half g_Wh[6 * CE * CE];                    // B-only: hi
__device__ __align__(128) float g_msgatt[CBS * CE], g_bm1eff[CE];

// ---------------- low-level helpers ----------------
__device__ __forceinline__ uint32_t smem_u32(const void* p) {
    uint32_t a;
    asm("{ .reg .u64 t; cvta.to.shared.u64 t, %1; cvt.u32.u64 %0, t; }" : "=r"(a) : "l"(p));
    return a;
}
__device__ __forceinline__ void cpasync16(uint32_t dst, const void* src) {
    asm volatile("cp.async.ca.shared.global [%0], [%1], 16;" :: "r"(dst), "l"(src));
}
__device__ __forceinline__ void cpcommit() { asm volatile("cp.async.commit_group;"); }
template <int N> __device__ __forceinline__ void cpwait() {
    asm volatile("cp.async.wait_group %0;" :: "n"(N));
}
__device__ __forceinline__ void ldsm4(uint32_t* r, uint32_t a) {
    asm volatile("ldmatrix.sync.aligned.m8n8.x4.shared.b16 {%0,%1,%2,%3}, [%4];"
                 : "=r"(r[0]), "=r"(r[1]), "=r"(r[2]), "=r"(r[3]) : "r"(a));
}
__device__ __forceinline__ void ldsm4t(uint32_t* r, uint32_t a) {
    asm volatile("ldmatrix.sync.aligned.m8n8.x4.trans.shared.b16 {%0,%1,%2,%3}, [%4];"
                 : "=r"(r[0]), "=r"(r[1]), "=r"(r[2]), "=r"(r[3]) : "r"(a));
}
__device__ __forceinline__ void mma16816(float* c, const uint32_t* a, const uint32_t* b) {
    asm volatile(
        "mma.sync.aligned.m16n8k16.row.col.f32.f16.f16.f32 "
        "{%0,%1,%2,%3}, {%4,%5,%6,%7}, {%8,%9}, {%0,%1,%2,%3};"
        : "+f"(c[0]), "+f"(c[1]), "+f"(c[2]), "+f"(c[3])
        : "r"(a[0]), "r"(a[1]), "r"(a[2]), "r"(a[3]), "r"(b[0]), "r"(b[1]));
}
__device__ __forceinline__ void split2(float v, __half& h, __half& l) {
    h = __float2half(v);
    l = __float2half(v - __half2float(h));
}

// ---------------- fp16-split tensor-core GEMM (2-pass: exact-A x fp16-B) ----------------
// C = alpha * A @ op(B) (+bias)(+add0)(gelu). A:[M][K] rm (hi+lo). TRANSB: B:[N][K] rm, else B:[K][N] rm (hi only).
// CTA tile 64x128, K-chunk 32, 2-stage cp.async pipeline, 8 warps (2x4) of 32x32.
// Output row mapping: o = coff + (r>>11)*segA + segB + (r&2047)*ldc + c
struct MP {
    const __half *Ah, *Al, *Bh;
    int lda, ldb, K;
    float alpha;
    const float *bias, *add0;
    float* outF;
    __half *outHi, *outLo;
    int ldc, gelu, zdiv;
    long long sAz, sAw, sBz, sBw, sCz, sCw;
    long long segA, segB;
};

constexpr int STG_A = 6144;    // 64 rows x 48 halves x 2B
constexpr int STG_B = 12288;   // max(128x48, 32x136) halves x 2B
constexpr int STAGE = 2 * STG_A + STG_B;  // 24576
constexpr int SMEM_BYTES = 2 * STAGE;     // 49152

// A tile: 64 rows x 32 halves, row stride 48 halves (96B); 1 chunk/thread
__device__ __forceinline__ void load_a(uint32_t sbase, const __half* G, int ld,
                                       int rowBase, int k0, int tid) {
    int row = tid >> 2, kc = tid & 3;
    cpasync16(sbase + (uint32_t)(row * 48 + kc * 8) * 2,
              G + (size_t)(rowBase + row) * ld + k0 + kc * 8);
}
// B (TN) tile: 128 rows x 32 halves, row stride 48 halves; 2 chunks/thread
__device__ __forceinline__ void load_bt(uint32_t sbase, const __half* G, int ld,
                                        int colBase, int k0, int tid) {
#pragma unroll
    for (int i = 0; i < 2; i++) {
        int c = tid + i * 256;
        int row = c >> 2, kc = c & 3;
        cpasync16(sbase + (uint32_t)(row * 48 + kc * 8) * 2,
                  G + (size_t)(colBase + row) * ld + k0 + kc * 8);
    }
}
// B (NN) tile: 32 k-rows x 128 n-cols, row stride 136 halves (272B); 2 chunks/thread
__device__ __forceinline__ void load_bn(uint32_t sbase, const __half* G, int ld,
                                        int colBase, int k0, int tid) {
#pragma unroll
    for (int i = 0; i < 2; i++) {
        int c = tid + i * 256;
        int kr = c >> 4, nc = c & 15;
        cpasync16(sbase + (uint32_t)(kr * 136 + nc * 8) * 2,
                  G + (size_t)(k0 + kr) * ld + colBase + nc * 8);
    }
}

template <bool TRANSB>
__global__ void __launch_bounds__(256, 2) mma_gemm(MP p) {
    extern __shared__ char smem[];
    const uint32_t sb = smem_u32(smem);
    const int tid = threadIdx.x, lane = tid & 31, wid = tid >> 5;
    const int warpM = wid >> 2, warpN = wid & 3;
    const int z = blockIdx.z, zq = z / p.zdiv, zr = z - zq * p.zdiv;
    const __half* Ah = p.Ah + (size_t)zq * p.sAz + (size_t)zr * p.sAw;
    const __half* Al = p.Al + (size_t)zq * p.sAz + (size_t)zr * p.sAw;
    const __half* Bh = p.Bh + (size_t)zq * p.sBz + (size_t)zr * p.sBw;
    const size_t coff = (size_t)zq * p.sCz + (size_t)zr * p.sCw;
    const int rowBase = blockIdx.y * 64, colBase = blockIdx.x * 128;

    float acc[2][4][4];
#pragma unroll
    for (int i = 0; i < 2; i++)
#pragma unroll
        for (int j = 0; j < 4; j++)
#pragma unroll
            for (int q = 0; q < 4; q++) acc[i][j][q] = 0.f;

    const int nchunk = p.K >> 5;

    auto loadStage = [&](int s, int k0) {
        uint32_t base = sb + s * STAGE;
        load_a(base, Ah, p.lda, rowBase, k0, tid);
        load_a(base + STG_A, Al, p.lda, rowBase, k0, tid);
        if (TRANSB) load_bt(base + 2 * STG_A, Bh, p.ldb, colBase, k0, tid);
        else        load_bn(base + 2 * STG_A, Bh, p.ldb, colBase, k0, tid);
        cpcommit();
    };

    loadStage(0, 0);
    for (int c = 0; c < nchunk; c++) {
        const int s = c & 1;
        if (c + 1 < nchunk) { loadStage(s ^ 1, (c + 1) << 5); cpwait<1>(); }
        else cpwait<0>();
        __syncthreads();

        const uint32_t base = sb + s * STAGE;
        const uint32_t aH = base, aL = base + STG_A;
        const uint32_t bH = base + 2 * STG_A;
#pragma unroll
        for (int kk = 0; kk < 2; kk++) {
            uint32_t ah[2][4], al[2][4], bh[4][2];
            const int ac = kk * 16 + (lane >> 4) * 8;
            const int ar = warpM * 32 + (lane & 15);
#pragma unroll
            for (int i = 0; i < 2; i++) {
                uint32_t off = (uint32_t)((ar + i * 16) * 48 + ac) * 2;
                ldsm4(ah[i], aH + off);
                ldsm4(al[i], aL + off);
            }
            if (TRANSB) {
#pragma unroll
                for (int jj = 0; jj < 2; jj++) {
                    int br = warpN * 32 + jj * 16 + (lane & 15);
                    uint32_t off = (uint32_t)(br * 48 + ac) * 2;
                    uint32_t r[4];
                    ldsm4(r, bH + off);
                    bh[jj * 2][0] = r[0]; bh[jj * 2][1] = r[2];
                    bh[jj * 2 + 1][0] = r[1]; bh[jj * 2 + 1][1] = r[3];
                }
            } else {
#pragma unroll
                for (int jj = 0; jj < 2; jj++) {
                    int br = kk * 16 + (lane & 15);
                    int bc = warpN * 32 + jj * 16 + (lane >> 4) * 8;
                    uint32_t off = (uint32_t)(br * 136 + bc) * 2;
                    uint32_t r[4];
                    ldsm4t(r, bH + off);
                    bh[jj * 2][0] = r[0]; bh[jj * 2][1] = r[1];
                    bh[jj * 2 + 1][0] = r[2]; bh[jj * 2 + 1][1] = r[3];
                }
            }
#pragma unroll
            for (int i = 0; i < 2; i++)
#pragma unroll
                for (int j = 0; j < 4; j++) {
                    mma16816(acc[i][j], ah[i], bh[j]);
                    mma16816(acc[i][j], al[i], bh[j]);
                }
        }
        __syncthreads();
    }

    // epilogue
    const float alpha = p.alpha;
#pragma unroll
    for (int i = 0; i < 2; i++) {
#pragma unroll
        for (int j = 0; j < 4; j++) {
            const int c0 = colBase + warpN * 32 + j * 8 + (lane & 3) * 2;
#pragma unroll
            for (int half = 0; half < 2; half++) {
                const int r = rowBase + warpM * 32 + i * 16 + (lane >> 2) + half * 8;
                float v0 = acc[i][j][half * 2] * alpha;
                float v1 = acc[i][j][half * 2 + 1] * alpha;
                if (p.bias) { v0 += p.bias[c0]; v1 += p.bias[c0 + 1]; }
                const size_t o = coff + (size_t)(r >> 11) * p.segA + p.segB
                               + (size_t)(r & 2047) * p.ldc + c0;
                if (p.add0) { v0 += p.add0[o]; v1 += p.add0[o + 1]; }
                if (p.gelu) {
                    v0 = 0.5f * v0 * (1.0f + erff(v0 * 0.70710678118654752440f));
                    v1 = 0.5f * v1 * (1.0f + erff(v1 * 0.70710678118654752440f));
                }
                if (p.outF) { float2 f2 = make_float2(v0, v1); *(float2*)(p.outF + o) = f2; }
                if (p.outHi) {
                    __half h0 = __float2half(v0), h1 = __float2half(v1);
                    __half2 hh; hh.x = h0; hh.y = h1;
                    *(__half2*)(p.outHi + o) = hh;
                    if (p.outLo) {
                        __half l0 = __float2half(v0 - __half2float(h0));
                        __half l1 = __float2half(v1 - __half2float(h1));
                        __half2 ll; ll.x = l0; ll.y = l1;
                        *(__half2*)(p.outLo + o) = ll;
                    }
                }
            }
        }
    }
}

// ---------------- softmax + head-mean + adjacency ----------------
__device__ __forceinline__ float blockMax256(float v, float* red) {
#pragma unroll
    for (int o = 16; o; o >>= 1) v = fmaxf(v, __shfl_xor_sync(0xffffffffu, v, o));
    if ((threadIdx.x & 31) == 0) red[threadIdx.x >> 5] = v;
    __syncthreads();
    if (threadIdx.x < 32) {
        float x = (threadIdx.x < 8) ? red[threadIdx.x] : -3.4e38f;
#pragma unroll
        for (int o = 4; o; o >>= 1) x = fmaxf(x, __shfl_xor_sync(0xffffffffu, x, o));
        if (threadIdx.x == 0) red[0] = x;
    }
    __syncthreads();
    float r = red[0];
    __syncthreads();
    return r;
}
__device__ __forceinline__ float blockSum256(float v, float* red) {
#pragma unroll
    for (int o = 16; o; o >>= 1) v += __shfl_xor_sync(0xffffffffu, v, o);
    if ((threadIdx.x & 31) == 0) red[threadIdx.x >> 5] = v;
    __syncthreads();
    if (threadIdx.x < 32) {
        float x = (threadIdx.x < 8) ? red[threadIdx.x] : 0.f;
#pragma unroll
        for (int o = 4; o; o >>= 1) x += __shfl_xor_sync(0xffffffffu, x, o);
        if (threadIdx.x == 0) red[0] = x;
    }
    __syncthreads();
    float r = red[0];
    __syncthreads();
    return r;
}

__global__ void __launch_bounds__(256) softmax_kernel() {
    const int i = blockIdx.x, b = blockIdx.y, tid = threadIdx.x;
    __shared__ float red[8];
    float wa[8];
#pragma unroll
    for (int u = 0; u < 8; u++) wa[u] = 0.f;
    for (int h = 0; h < CH; h++) {
        const float* row = g_scores + (((size_t)(b * CH + h) * CS) + i) * CS;
        float vals[8];
        float lmax = -3.4e38f;
#pragma unroll
        for (int u = 0; u < 8; u++) { vals[u] = row[tid + 256 * u]; lmax = fmaxf(lmax, vals[u]); }
        float m = blockMax256(lmax, red);
        float lsum = 0.f;
#pragma unroll
        for (int u = 0; u < 8; u++) { vals[u] = expf(vals[u] - m); lsum += vals[u]; }
        float inv = 1.0f / blockSum256(lsum, red);
#pragma unroll
        for (int u = 0; u < 8; u++) wa[u] += vals[u] * inv;
    }
    float cnt = 0.f;
#pragma unroll
    for (int u = 0; u < 8; u++) {
        float wm = wa[u] * (1.0f / CH);
        wa[u] = wm;
        cnt += (wm > 0.1f) ? 1.f : 0.f;
    }
    float nn = fmaxf(blockSum256(cnt, red), 1.0f);
    float invn = 1.0f / nn;
    // combined A row: [wk(0..2047) | wm(2048..4095)]
    size_t base = ((size_t)b * CS + i) * (size_t)(2 * CS);
#pragma unroll
    for (int u = 0; u < 8; u++) {
        int j = tid + 256 * u;
        float wm = wa[u];
        float wk = (wm > 0.1f) ? wm * invn : 0.f;
        __half h, l;
        split2(wk, h, l); g_wh[base + j] = h;        g_wl[base + j] = l;
        split2(wm, h, l); g_wh[base + 2048 + j] = h; g_wl[base + 2048 + j] = l;
    }
}

// ---------------- prep kernels ----------------
__global__ void xsplit_kernel(const float* __restrict__ x) {
    int idx = blockIdx.x * 256 + threadIdx.x;
    if (idx < CBS * CE) {
        __half h, l;
        split2(x[idx], h, l);
        g_xh[idx] = h; g_xl[idx] = l;
        int b = idx >> 20;                 // CS*CE = 2^20
        int within = idx & ((CS * CE) - 1);
        g_xvh[(size_t)b * (2 * CS * CE) + within] = h;
    }
}
__global__ void wconv_kernel(const float* __restrict__ src, int ldin,
                             __half* __restrict__ dh) {
    int idx = blockIdx.x * 256 + threadIdx.x;
    if (idx < CE * CE) {
        int r = idx >> 9, c = idx & 511;
        dh[idx] = __float2half(src[(size_t)r * ldin + c]);
    }
}
__global__ void bm1eff_kernel(const float* __restrict__ Wm1, const float* __restrict__ bm1) {
    int e = blockIdx.x * 256 + threadIdx.x;
    if (e < CE) {
        float s = 0.f;
#pragma unroll
        for (int c = 0; c < CH; c++) s += Wm1[(size_t)e * (CE + CH) + CE + c];
        g_bm1eff[e] = bm1[e] + s * (1.0f / CS);
    }
}

// ---------------- host ----------------
static void run_mm(bool transb,
                   const __half* Ah, const __half* Al, int lda,
                   const __half* Bh, int ldb,
                   int M, int N, int K, float alpha,
                   const float* bias, const float* add0,
                   float* outF, __half* outHi, __half* outLo,
                   int ldc, int gelu, int zcount, int zdiv,
                   long long sAz, long long sAw, long long sBz, long long sBw,
                   long long sCz, long long sCw,
                   long long segA = -1, long long segB = 0) {
    MP p;
    p.Ah = Ah; p.Al = Al; p.Bh = Bh;
    p.lda = lda; p.ldb = ldb; p.K = K; p.alpha = alpha;
    p.bias = bias; p.add0 = add0;
    p.outF = outF; p.outHi = outHi; p.outLo = outLo;
    p.ldc = ldc; p.gelu = gelu; p.zdiv = zdiv;
    p.sAz = sAz; p.sAw = sAw; p.sBz = sBz; p.sBw = sBw; p.sCz = sCz; p.sCw = sCw;
    p.segA = (segA < 0) ? (long long)2048 * ldc : segA;
    p.segB = segB;
    dim3 grid(N / 128, M / 64, zcount);
    if (transb) mma_gemm<true><<<grid, 256, SMEM_BYTES>>>(p);
    else        mma_gemm<false><<<grid, 256, SMEM_BYTES>>>(p);
}

extern "C" void kernel_launch(void* const* d_in, const int* in_sizes, int n_in,
                              void* d_out, int out_size) {
    const float* x   = (const float*)d_in[0];
    const float* Wq  = (const float*)d_in[1];
    const float* bq  = (const float*)d_in[2];
    const float* Wk  = (const float*)d_in[3];
    const float* bk  = (const float*)d_in[4];
    const float* Wv  = (const float*)d_in[5];
    const float* bv  = (const float*)d_in[6];
    const float* Wm1 = (const float*)d_in[7];
    const float* bm1 = (const float*)d_in[8];
    const float* Wm2 = (const float*)d_in[9];
    const float* bm2 = (const float*)d_in[10];
    const float* Wo  = (const float*)d_in[11];
    const float* bo  = (const float*)d_in[12];
    float* out = (float*)d_out;

    cudaFuncSetAttribute(mma_gemm<true>,  cudaFuncAttributeMaxDynamicSharedMemorySize, SMEM_BYTES);
    cudaFuncSetAttribute(mma_gemm<false>, cudaFuncAttributeMaxDynamicSharedMemorySize, SMEM_BYTES);

    float *sc, *ma, *b1e;
    __half *xh, *xl, *qh, *ql, *kh, *xvh;
    __half *t1h, *t1l, *t2h, *t2l, *wh, *wl, *Wh;
    cudaGetSymbolAddress((void**)&sc, g_scores);
    cudaGetSymbolAddress((void**)&ma, g_msgatt);
    cudaGetSymbolAddress((void**)&b1e, g_bm1eff);
    cudaGetSymbolAddress((void**)&xh, g_xh);   cudaGetSymbolAddress((void**)&xl, g_xl);
    cudaGetSymbolAddress((void**)&qh, g_qh);   cudaGetSymbolAddress((void**)&ql, g_ql);
    cudaGetSymbolAddress((void**)&kh, g_kh);
    cudaGetSymbolAddress((void**)&xvh, g_xvh);
    cudaGetSymbolAddress((void**)&t1h, g_t1h); cudaGetSymbolAddress((void**)&t1l, g_t1l);
    cudaGetSymbolAddress((void**)&t2h, g_t2h); cudaGetSymbolAddress((void**)&t2l, g_t2l);
    cudaGetSymbolAddress((void**)&wh, g_wh);   cudaGetSymbolAddress((void**)&wl, g_wl);
    cudaGetSymbolAddress((void**)&Wh, g_Wh);

    const long long SE = (long long)CS * CE;
    const long long SS = (long long)CS * CS;
    const int WN = CE * CE;

    // prep: splits + effective bm1
    xsplit_kernel<<<(CBS * CE + 255) / 256, 256>>>(x);
    int wgrid = (CE * CE + 255) / 256;
    wconv_kernel<<<wgrid, 256>>>(Wq, CE, Wh + 0 * WN);
    wconv_kernel<<<wgrid, 256>>>(Wk, CE, Wh + 1 * WN);
    wconv_kernel<<<wgrid, 256>>>(Wv, CE, Wh + 2 * WN);
    wconv_kernel<<<wgrid, 256>>>(Wm1, CE + CH, Wh + 3 * WN);
    wconv_kernel<<<wgrid, 256>>>(Wm2, CE, Wh + 4 * WN);
    wconv_kernel<<<wgrid, 256>>>(Wo, CE, Wh + 5 * WN);
    bm1eff_kernel<<<2, 256>>>(Wm1, bm1);

    // q (hi+lo), k (hi only), v -> stacked [x;v] (hi only, segment 1)
    run_mm(true, xh, xl, CE, Wh + 0 * WN, CE, CBS, CE, CE, 1.f, bq,
           nullptr, nullptr, qh, ql, CE, 0, 1, 1, 0, 0, 0, 0, 0, 0);
    run_mm(true, xh, xl, CE, Wh + 1 * WN, CE, CBS, CE, CE, 1.f, bk,
           nullptr, nullptr, kh, nullptr, CE, 0, 1, 1, 0, 0, 0, 0, 0, 0);
    run_mm(true, xh, xl, CE, Wh + 2 * WN, CE, CBS, CE, CE, 1.f, bv,
           nullptr, nullptr, xvh, nullptr, CE, 0, 1, 1, 0, 0, 0, 0, 0, 0,
           (long long)2 * CS * CE /*segA: batch block*/, (long long)CS * CE /*segB: v segment*/);

    // scores = 0.125 * q_h @ k_h^T  (z = b*8 + h)
    run_mm(true, qh, ql, CE, kh, CE, CS, CS, 64, 0.125f, nullptr,
           nullptr, sc, nullptr, nullptr, CS, 0,
           CB * CH, CH, SE, 64, SE, 64, (long long)CH * SS, SS);

    // softmax / adjacency -> combined [wk | wm] (hi+lo)
    {
        dim3 g(CS, CB);
        softmax_kernel<<<g, 256>>>();
    }

    // msg+att = [wk|wm] @ [x;v]   (K = 4096, per batch)
    run_mm(false, wh, wl, 2 * CS, xvh, CE, CS, CE, 2 * CS, 1.f, nullptr,
           nullptr, ma, nullptr, nullptr, CE, 0,
           CB, 1, (long long)CS * 2 * CS, 0, (long long)2 * CS * CE, 0, SE, 0);

    // t1 = gelu(x @ Wm1'^T + bm1eff)
    run_mm(true, xh, xl, CE, Wh + 3 * WN, CE, CBS, CE, CE, 1.f, b1e,
           nullptr, nullptr, t1h, t1l, CE, 1, 1, 1, 0, 0, 0, 0, 0, 0);

    // t2 = t1 @ Wm2^T + bm2 + (msg+att)
    run_mm(true, t1h, t1l, CE, Wh + 4 * WN, CE, CBS, CE, CE, 1.f, bm2,
           ma, nullptr, t2h, t2l, CE, 0, 1, 1, 0, 0, 0, 0, 0, 0);

    // out = t2 @ Wo^T + bo
    run_mm(true, t2h, t2l, CE, Wh + 5 * WN, CE, CBS, CE, CE, 1.f, bo,
           nullptr, out, nullptr, nullptr, CE, 0, 1, 1, 0, 0, 0, 0, 0, 0);
}

// round 11
// speedup vs baseline: 1.2391x; 1.2391x over previous
#include <cuda_runtime.h>
#include <cuda_bf16.h>
#include <cuda_fp16.h>
#include <cstdint>
#include <math.h>

constexpr int CB = 2, CS = 2048, CE = 512, CH = 8, CBS = CB * CS;

// ---------------- scratch (device globals; allocation-free) ----------------
__device__ __align__(128) __half g_scores[(size_t)CB * CH * CS * CS];  // 134 MB fp16
__device__ __align__(128) __nv_bfloat16 g_xh[CBS * CE], g_xl[CBS * CE];
__device__ __align__(128) __nv_bfloat16 g_qh[CBS * CE], g_ql[CBS * CE];
__device__ __align__(128) __nv_bfloat16 g_kh[CBS * CE], g_kl[CBS * CE];
// stacked [x ; v] per batch: [b][0..2047]=x, [b][2048..4095]=v, width CE
__device__ __align__(128) __nv_bfloat16 g_xvh[(size_t)CB * 2 * CS * CE], g_xvl[(size_t)CB * 2 * CS * CE];
__device__ __align__(128) __nv_bfloat16 g_t1h[CBS * CE], g_t1l[CBS * CE];
__device__ __align__(128) __nv_bfloat16 g_t2h[CBS * CE], g_t2l[CBS * CE];
// combined weights [b][i][0..2047]=wk, [b][i][2048..4095]=wm
__device__ __align__(128) __nv_bfloat16 g_wh[(size_t)CB * CS * 2 * CS], g_wl[(size_t)CB * CS * 2 * CS];
__device__ __align__(128) __nv_bfloat16 g_Wh[6 * CE * CE], g_Wl[6 * CE * CE];
__device__ __align__(128) float g_msgatt[CBS * CE], g_bm1eff[CE];

// ---------------- low-level helpers ----------------
__device__ __forceinline__ uint32_t smem_u32(const void* p) {
    uint32_t a;
    asm("{ .reg .u64 t; cvta.to.shared.u64 t, %1; cvt.u32.u64 %0, t; }" : "=r"(a) : "l"(p));
    return a;
}
__device__ __forceinline__ void cpasync16(uint32_t dst, const void* src) {
    asm volatile("cp.async.ca.shared.global [%0], [%1], 16;" :: "r"(dst), "l"(src));
}
__device__ __forceinline__ void cpcommit() { asm volatile("cp.async.commit_group;"); }
template <int N> __device__ __forceinline__ void cpwait() {
    asm volatile("cp.async.wait_group %0;" :: "n"(N));
}
__device__ __forceinline__ void ldsm4(uint32_t* r, uint32_t a) {
    asm volatile("ldmatrix.sync.aligned.m8n8.x4.shared.b16 {%0,%1,%2,%3}, [%4];"
                 : "=r"(r[0]), "=r"(r[1]), "=r"(r[2]), "=r"(r[3]) : "r"(a));
}
__device__ __forceinline__ void ldsm4t(uint32_t* r, uint32_t a) {
    asm volatile("ldmatrix.sync.aligned.m8n8.x4.trans.shared.b16 {%0,%1,%2,%3}, [%4];"
                 : "=r"(r[0]), "=r"(r[1]), "=r"(r[2]), "=r"(r[3]) : "r"(a));
}
__device__ __forceinline__ void mma16816(float* c, const uint32_t* a, const uint32_t* b) {
    asm volatile(
        "mma.sync.aligned.m16n8k16.row.col.f32.bf16.bf16.f32 "
        "{%0,%1,%2,%3}, {%4,%5,%6,%7}, {%8,%9}, {%0,%1,%2,%3};"
        : "+f"(c[0]), "+f"(c[1]), "+f"(c[2]), "+f"(c[3])
        : "r"(a[0]), "r"(a[1]), "r"(a[2]), "r"(a[3]), "r"(b[0]), "r"(b[1]));
}
__device__ __forceinline__ void split2(float v, __nv_bfloat16& h, __nv_bfloat16& l) {
    h = __float2bfloat16(v);
    l = __float2bfloat16(v - __bfloat162float(h));
}

// ---------------- bf16-split tensor-core GEMM ----------------
// C = alpha * A @ op(B) (+bias)(+add0)(gelu). A:[M][K] rm. TRANSB: B:[N][K] rm, else B:[K][N] rm.
// CTA tile 64x128, K-chunk 32, 2-stage cp.async pipeline, 8 warps (2x4) of 32x32.
// Output row mapping: o = coff + (r>>11)*segA + segB + (r&2047)*ldc + c
struct MP {
    const __nv_bfloat16 *Ah, *Al, *Bh, *Bl;
    int lda, ldb, K;
    float alpha;
    const float *bias, *add0;
    float* outF;
    __half* outHalf;
    __nv_bfloat16 *outHi, *outLo;
    int ldc, gelu, zdiv;
    long long sAz, sAw, sBz, sBw, sCz, sCw;
    long long segA, segB;
};

constexpr int STG_A = 6144;    // 64 rows x 48 halves x 2B
constexpr int STG_B = 12288;   // max(128x48, 32x136) halves x 2B
constexpr int STAGE = 2 * STG_A + 2 * STG_B;  // 36864
constexpr int SMEM_BYTES = 2 * STAGE;          // 73728

// A tile: 64 rows x 32 halves, row stride 48 halves (96B); 1 chunk/thread
__device__ __forceinline__ void load_a(uint32_t sbase, const __nv_bfloat16* G, int ld,
                                       int rowBase, int k0, int tid) {
    int row = tid >> 2, kc = tid & 3;
    cpasync16(sbase + (uint32_t)(row * 48 + kc * 8) * 2,
              G + (size_t)(rowBase + row) * ld + k0 + kc * 8);
}
// B (TN) tile: 128 rows x 32 halves, row stride 48 halves; 2 chunks/thread
__device__ __forceinline__ void load_bt(uint32_t sbase, const __nv_bfloat16* G, int ld,
                                        int colBase, int k0, int tid) {
#pragma unroll
    for (int i = 0; i < 2; i++) {
        int c = tid + i * 256;
        int row = c >> 2, kc = c & 3;
        cpasync16(sbase + (uint32_t)(row * 48 + kc * 8) * 2,
                  G + (size_t)(colBase + row) * ld + k0 + kc * 8);
    }
}
// B (NN) tile: 32 k-rows x 128 n-cols, row stride 136 halves (272B); 2 chunks/thread
__device__ __forceinline__ void load_bn(uint32_t sbase, const __nv_bfloat16* G, int ld,
                                        int colBase, int k0, int tid) {
#pragma unroll
    for (int i = 0; i < 2; i++) {
        int c = tid + i * 256;
        int kr = c >> 4, nc = c & 15;
        cpasync16(sbase + (uint32_t)(kr * 136 + nc * 8) * 2,
                  G + (size_t)(k0 + kr) * ld + colBase + nc * 8);
    }
}

template <bool TRANSB>
__global__ void __launch_bounds__(256, 2) mma_gemm(MP p) {
    extern __shared__ char smem[];
    const uint32_t sb = smem_u32(smem);
    const int tid = threadIdx.x, lane = tid & 31, wid = tid >> 5;
    const int warpM = wid >> 2, warpN = wid & 3;
    const int z = blockIdx.z, zq = z / p.zdiv, zr = z - zq * p.zdiv;
    const __nv_bfloat16* Ah = p.Ah + (size_t)zq * p.sAz + (size_t)zr * p.sAw;
    const __nv_bfloat16* Al = p.Al + (size_t)zq * p.sAz + (size_t)zr * p.sAw;
    const __nv_bfloat16* Bh = p.Bh + (size_t)zq * p.sBz + (size_t)zr * p.sBw;
    const __nv_bfloat16* Bl = p.Bl + (size_t)zq * p.sBz + (size_t)zr * p.sBw;
    const size_t coff = (size_t)zq * p.sCz + (size_t)zr * p.sCw;
    const int rowBase = blockIdx.y * 64, colBase = blockIdx.x * 128;

    float acc[2][4][4];
#pragma unroll
    for (int i = 0; i < 2; i++)
#pragma unroll
        for (int j = 0; j < 4; j++)
#pragma unroll
            for (int q = 0; q < 4; q++) acc[i][j][q] = 0.f;

    const int nchunk = p.K >> 5;

    auto loadStage = [&](int s, int k0) {
        uint32_t base = sb + s * STAGE;
        load_a(base, Ah, p.lda, rowBase, k0, tid);
        load_a(base + STG_A, Al, p.lda, rowBase, k0, tid);
        if (TRANSB) {
            load_bt(base + 2 * STG_A, Bh, p.ldb, colBase, k0, tid);
            load_bt(base + 2 * STG_A + STG_B, Bl, p.ldb, colBase, k0, tid);
        } else {
            load_bn(base + 2 * STG_A, Bh, p.ldb, colBase, k0, tid);
            load_bn(base + 2 * STG_A + STG_B, Bl, p.ldb, colBase, k0, tid);
        }
        cpcommit();
    };

    loadStage(0, 0);
    for (int c = 0; c < nchunk; c++) {
        const int s = c & 1;
        if (c + 1 < nchunk) { loadStage(s ^ 1, (c + 1) << 5); cpwait<1>(); }
        else cpwait<0>();
        __syncthreads();

        const uint32_t base = sb + s * STAGE;
        const uint32_t aH = base, aL = base + STG_A;
        const uint32_t bH = base + 2 * STG_A, bL = base + 2 * STG_A + STG_B;
#pragma unroll
        for (int kk = 0; kk < 2; kk++) {
            uint32_t ah[2][4], al[2][4], bh[4][2], bl[4][2];
            const int ac = kk * 16 + (lane >> 4) * 8;
            const int ar = warpM * 32 + (lane & 15);
#pragma unroll
            for (int i = 0; i < 2; i++) {
                uint32_t off = (uint32_t)((ar + i * 16) * 48 + ac) * 2;
                ldsm4(ah[i], aH + off);
                ldsm4(al[i], aL + off);
            }
            if (TRANSB) {
#pragma unroll
                for (int jj = 0; jj < 2; jj++) {
                    int br = warpN * 32 + jj * 16 + (lane & 15);
                    uint32_t off = (uint32_t)(br * 48 + ac) * 2;
                    uint32_t r[4], s2[4];
                    ldsm4(r, bH + off);
                    ldsm4(s2, bL + off);
                    bh[jj * 2][0] = r[0]; bh[jj * 2][1] = r[2];
                    bh[jj * 2 + 1][0] = r[1]; bh[jj * 2 + 1][1] = r[3];
                    bl[jj * 2][0] = s2[0]; bl[jj * 2][1] = s2[2];
                    bl[jj * 2 + 1][0] = s2[1]; bl[jj * 2 + 1][1] = s2[3];
                }
            } else {
#pragma unroll
                for (int jj = 0; jj < 2; jj++) {
                    int br = kk * 16 + (lane & 15);
                    int bc = warpN * 32 + jj * 16 + (lane >> 4) * 8;
                    uint32_t off = (uint32_t)(br * 136 + bc) * 2;
                    uint32_t r[4], s2[4];
                    ldsm4t(r, bH + off);
                    ldsm4t(s2, bL + off);
                    bh[jj * 2][0] = r[0]; bh[jj * 2][1] = r[1];
                    bh[jj * 2 + 1][0] = r[2]; bh[jj * 2 + 1][1] = r[3];
                    bl[jj * 2][0] = s2[0]; bl[jj * 2][1] = s2[1];
                    bl[jj * 2 + 1][0] = s2[2]; bl[jj * 2 + 1][1] = s2[3];
                }
            }
#pragma unroll
            for (int i = 0; i < 2; i++)
#pragma unroll
                for (int j = 0; j < 4; j++) {
                    mma16816(acc[i][j], ah[i], bh[j]);
                    mma16816(acc[i][j], ah[i], bl[j]);
                    mma16816(acc[i][j], al[i], bh[j]);
                }
        }
        __syncthreads();
    }

    // epilogue
    const float alpha = p.alpha;
#pragma unroll
    for (int i = 0; i < 2; i++) {
#pragma unroll
        for (int j = 0; j < 4; j++) {
            const int c0 = colBase + warpN * 32 + j * 8 + (lane & 3) * 2;
#pragma unroll
            for (int half = 0; half < 2; half++) {
                const int r = rowBase + warpM * 32 + i * 16 + (lane >> 2) + half * 8;
                float v0 = acc[i][j][half * 2] * alpha;
                float v1 = acc[i][j][half * 2 + 1] * alpha;
                if (p.bias) { v0 += p.bias[c0]; v1 += p.bias[c0 + 1]; }
                const size_t o = coff + (size_t)(r >> 11) * p.segA + p.segB
                               + (size_t)(r & 2047) * p.ldc + c0;
                if (p.add0) { v0 += p.add0[o]; v1 += p.add0[o + 1]; }
                if (p.gelu) {
                    v0 = 0.5f * v0 * (1.0f + erff(v0 * 0.70710678118654752440f));
                    v1 = 0.5f * v1 * (1.0f + erff(v1 * 0.70710678118654752440f));
                }
                if (p.outF) { float2 f2 = make_float2(v0, v1); *(float2*)(p.outF + o) = f2; }
                if (p.outHalf) {
                    __half2 hp; hp.x = __float2half(v0); hp.y = __float2half(v1);
                    *(__half2*)(p.outHalf + o) = hp;
                }
                if (p.outHi) {
                    __nv_bfloat16 h0, l0, h1, l1;
                    split2(v0, h0, l0); split2(v1, h1, l1);
                    __nv_bfloat162 hh; hh.x = h0; hh.y = h1;
                    __nv_bfloat162 ll; ll.x = l0; ll.y = l1;
                    *(__nv_bfloat162*)(p.outHi + o) = hh;
                    *(__nv_bfloat162*)(p.outLo + o) = ll;
                }
            }
        }
    }
}

// ---------------- softmax + head-mean + adjacency ----------------
__device__ __forceinline__ float blockMax256(float v, float* red) {
#pragma unroll
    for (int o = 16; o; o >>= 1) v = fmaxf(v, __shfl_xor_sync(0xffffffffu, v, o));
    if ((threadIdx.x & 31) == 0) red[threadIdx.x >> 5] = v;
    __syncthreads();
    if (threadIdx.x < 32) {
        float x = (threadIdx.x < 8) ? red[threadIdx.x] : -3.4e38f;
#pragma unroll
        for (int o = 4; o; o >>= 1) x = fmaxf(x, __shfl_xor_sync(0xffffffffu, x, o));
        if (threadIdx.x == 0) red[0] = x;
    }
    __syncthreads();
    float r = red[0];
    __syncthreads();
    return r;
}
__device__ __forceinline__ float blockSum256(float v, float* red) {
#pragma unroll
    for (int o = 16; o; o >>= 1) v += __shfl_xor_sync(0xffffffffu, v, o);
    if ((threadIdx.x & 31) == 0) red[threadIdx.x >> 5] = v;
    __syncthreads();
    if (threadIdx.x < 32) {
        float x = (threadIdx.x < 8) ? red[threadIdx.x] : 0.f;
#pragma unroll
        for (int o = 4; o; o >>= 1) x += __shfl_xor_sync(0xffffffffu, x, o);
        if (threadIdx.x == 0) red[0] = x;
    }
    __syncthreads();
    float r = red[0];
    __syncthreads();
    return r;
}

// scores are fp16; reads/writes vectorized by pairs (j = 2*jp, 2*jp+1)
__global__ void __launch_bounds__(256) softmax_kernel() {
    const int i = blockIdx.x, b = blockIdx.y, tid = threadIdx.x;
    __shared__ float red[8];
    float wa[8];
#pragma unroll
    for (int u = 0; u < 8; u++) wa[u] = 0.f;
    for (int h = 0; h < CH; h++) {
        const __half2* row = (const __half2*)(g_scores + (((size_t)(b * CH + h) * CS) + i) * CS);
        float vals[8];
        float lmax = -3.4e38f;
#pragma unroll
        for (int u = 0; u < 4; u++) {
            __half2 pr = row[tid + 256 * u];
            float a0 = __half2float(pr.x), a1 = __half2float(pr.y);
            vals[2 * u] = a0; vals[2 * u + 1] = a1;
            lmax = fmaxf(lmax, fmaxf(a0, a1));
        }
        float m = blockMax256(lmax, red);
        float lsum = 0.f;
#pragma unroll
        for (int u = 0; u < 8; u++) { vals[u] = expf(vals[u] - m); lsum += vals[u]; }
        float inv = 1.0f / blockSum256(lsum, red);
#pragma unroll
        for (int u = 0; u < 8; u++) wa[u] += vals[u] * inv;
    }
    float cnt = 0.f;
#pragma unroll
    for (int u = 0; u < 8; u++) {
        float wm = wa[u] * (1.0f / CH);
        wa[u] = wm;
        cnt += (wm > 0.1f) ? 1.f : 0.f;
    }
    float nn = fmaxf(blockSum256(cnt, red), 1.0f);
    float invn = 1.0f / nn;
    // combined A row: [wk(0..2047) | wm(2048..4095)], paired stores
    size_t base = ((size_t)b * CS + i) * (size_t)(2 * CS);
#pragma unroll
    for (int u = 0; u < 4; u++) {
        int jp = tid + 256 * u;  // pair index, elements 2jp, 2jp+1
        float wm0 = wa[2 * u], wm1 = wa[2 * u + 1];
        float wk0 = (wm0 > 0.1f) ? wm0 * invn : 0.f;
        float wk1 = (wm1 > 0.1f) ? wm1 * invn : 0.f;
        __nv_bfloat16 h0, l0, h1, l1;
        split2(wk0, h0, l0); split2(wk1, h1, l1);
        __nv_bfloat162 hh, ll;
        hh.x = h0; hh.y = h1; ll.x = l0; ll.y = l1;
        *(__nv_bfloat162*)(g_wh + base + 2 * jp) = hh;
        *(__nv_bfloat162*)(g_wl + base + 2 * jp) = ll;
        split2(wm0, h0, l0); split2(wm1, h1, l1);
        hh.x = h0; hh.y = h1; ll.x = l0; ll.y = l1;
        *(__nv_bfloat162*)(g_wh + base + 2048 + 2 * jp) = hh;
        *(__nv_bfloat162*)(g_wl + base + 2048 + 2 * jp) = ll;
    }
}

// ---------------- prep kernels ----------------
__global__ void xsplit_kernel(const float* __restrict__ x) {
    int idx = blockIdx.x * 256 + threadIdx.x;
    if (idx < CBS * CE) {
        __nv_bfloat16 h, l;
        split2(x[idx], h, l);
        g_xh[idx] = h; g_xl[idx] = l;
        int b = idx >> 20;                 // CS*CE = 2^20
        int within = idx & ((CS * CE) - 1);
        size_t o = (size_t)b * (2 * CS * CE) + within;
        g_xvh[o] = h; g_xvl[o] = l;
    }
}
__global__ void wconv_kernel(const float* __restrict__ src, int ldin,
                             __nv_bfloat16* __restrict__ dh, __nv_bfloat16* __restrict__ dl) {
    int idx = blockIdx.x * 256 + threadIdx.x;
    if (idx < CE * CE) {
        int r = idx >> 9, c = idx & 511;
        __nv_bfloat16 h, l;
        split2(src[(size_t)r * ldin + c], h, l);
        dh[idx] = h; dl[idx] = l;
    }
}
__global__ void bm1eff_kernel(const float* __restrict__ Wm1, const float* __restrict__ bm1) {
    int e = blockIdx.x * 256 + threadIdx.x;
    if (e < CE) {
        float s = 0.f;
#pragma unroll
        for (int c = 0; c < CH; c++) s += Wm1[(size_t)e * (CE + CH) + CE + c];
        g_bm1eff[e] = bm1[e] + s * (1.0f / CS);
    }
}

// ---------------- host ----------------
static void run_mm(bool transb,
                   const __nv_bfloat16* Ah, const __nv_bfloat16* Al, int lda,
                   const __nv_bfloat16* Bh, const __nv_bfloat16* Bl, int ldb,
                   int M, int N, int K, float alpha,
                   const float* bias, const float* add0,
                   float* outF, __half* outHalf,
                   __nv_bfloat16* outHi, __nv_bfloat16* outLo,
                   int ldc, int gelu, int zcount, int zdiv,
                   long long sAz, long long sAw, long long sBz, long long sBw,
                   long long sCz, long long sCw,
                   long long segA = -1, long long segB = 0) {
    MP p;
    p.Ah = Ah; p.Al = Al; p.Bh = Bh; p.Bl = Bl;
    p.lda = lda; p.ldb = ldb; p.K = K; p.alpha = alpha;
    p.bias = bias; p.add0 = add0;
    p.outF = outF; p.outHalf = outHalf; p.outHi = outHi; p.outLo = outLo;
    p.ldc = ldc; p.gelu = gelu; p.zdiv = zdiv;
    p.sAz = sAz; p.sAw = sAw; p.sBz = sBz; p.sBw = sBw; p.sCz = sCz; p.sCw = sCw;
    p.segA = (segA < 0) ? (long long)2048 * ldc : segA;
    p.segB = segB;
    dim3 grid(N / 128, M / 64, zcount);
    if (transb) mma_gemm<true><<<grid, 256, SMEM_BYTES>>>(p);
    else        mma_gemm<false><<<grid, 256, SMEM_BYTES>>>(p);
}

extern "C" void kernel_launch(void* const* d_in, const int* in_sizes, int n_in,
                              void* d_out, int out_size) {
    const float* x   = (const float*)d_in[0];
    const float* Wq  = (const float*)d_in[1];
    const float* bq  = (const float*)d_in[2];
    const float* Wk  = (const float*)d_in[3];
    const float* bk  = (const float*)d_in[4];
    const float* Wv  = (const float*)d_in[5];
    const float* bv  = (const float*)d_in[6];
    const float* Wm1 = (const float*)d_in[7];
    const float* bm1 = (const float*)d_in[8];
    const float* Wm2 = (const float*)d_in[9];
    const float* bm2 = (const float*)d_in[10];
    const float* Wo  = (const float*)d_in[11];
    const float* bo  = (const float*)d_in[12];
    float* out = (float*)d_out;

    cudaFuncSetAttribute(mma_gemm<true>,  cudaFuncAttributeMaxDynamicSharedMemorySize, SMEM_BYTES);
    cudaFuncSetAttribute(mma_gemm<false>, cudaFuncAttributeMaxDynamicSharedMemorySize, SMEM_BYTES);

    float *ma, *b1e;
    __half* sc;
    __nv_bfloat16 *xh, *xl, *qh, *ql, *kh, *kl, *xvh, *xvl;
    __nv_bfloat16 *t1h, *t1l, *t2h, *t2l, *wh, *wl, *Wh, *Wl;
    cudaGetSymbolAddress((void**)&sc, g_scores);
    cudaGetSymbolAddress((void**)&ma, g_msgatt);
    cudaGetSymbolAddress((void**)&b1e, g_bm1eff);
    cudaGetSymbolAddress((void**)&xh, g_xh);   cudaGetSymbolAddress((void**)&xl, g_xl);
    cudaGetSymbolAddress((void**)&qh, g_qh);   cudaGetSymbolAddress((void**)&ql, g_ql);
    cudaGetSymbolAddress((void**)&kh, g_kh);   cudaGetSymbolAddress((void**)&kl, g_kl);
    cudaGetSymbolAddress((void**)&xvh, g_xvh); cudaGetSymbolAddress((void**)&xvl, g_xvl);
    cudaGetSymbolAddress((void**)&t1h, g_t1h); cudaGetSymbolAddress((void**)&t1l, g_t1l);
    cudaGetSymbolAddress((void**)&t2h, g_t2h); cudaGetSymbolAddress((void**)&t2l, g_t2l);
    cudaGetSymbolAddress((void**)&wh, g_wh);   cudaGetSymbolAddress((void**)&wl, g_wl);
    cudaGetSymbolAddress((void**)&Wh, g_Wh);   cudaGetSymbolAddress((void**)&Wl, g_Wl);

    const long long SE = (long long)CS * CE;
    const long long SS = (long long)CS * CS;
    const int WN = CE * CE;

    // prep: splits + effective bm1
    xsplit_kernel<<<(CBS * CE + 255) / 256, 256>>>(x);
    int wgrid = (CE * CE + 255) / 256;
    wconv_kernel<<<wgrid, 256>>>(Wq, CE, Wh + 0 * WN, Wl + 0 * WN);
    wconv_kernel<<<wgrid, 256>>>(Wk, CE, Wh + 1 * WN, Wl + 1 * WN);
    wconv_kernel<<<wgrid, 256>>>(Wv, CE, Wh + 2 * WN, Wl + 2 * WN);
    wconv_kernel<<<wgrid, 256>>>(Wm1, CE + CH, Wh + 3 * WN, Wl + 3 * WN);
    wconv_kernel<<<wgrid, 256>>>(Wm2, CE, Wh + 4 * WN, Wl + 4 * WN);
    wconv_kernel<<<wgrid, 256>>>(Wo, CE, Wh + 5 * WN, Wl + 5 * WN);
    bm1eff_kernel<<<2, 256>>>(Wm1, bm1);

    // q, k projections (row-major); v projection written into stacked [x;v] (segment 1)
    run_mm(true, xh, xl, CE, Wh + 0 * WN, Wl + 0 * WN, CE, CBS, CE, CE, 1.f, bq,
           nullptr, nullptr, nullptr, qh, ql, CE, 0, 1, 1, 0, 0, 0, 0, 0, 0);
    run_mm(true, xh, xl, CE, Wh + 1 * WN, Wl + 1 * WN, CE, CBS, CE, CE, 1.f, bk,
           nullptr, nullptr, nullptr, kh, kl, CE, 0, 1, 1, 0, 0, 0, 0, 0, 0);
    run_mm(true, xh, xl, CE, Wh + 2 * WN, Wl + 2 * WN, CE, CBS, CE, CE, 1.f, bv,
           nullptr, nullptr, nullptr, xvh, xvl, CE, 0, 1, 1, 0, 0, 0, 0, 0, 0,
           (long long)2 * CS * CE /*segA: batch block*/, (long long)CS * CE /*segB: v segment*/);

    // scores (fp16) = 0.125 * q_h @ k_h^T  (z = b*8 + h)
    run_mm(true, qh, ql, CE, kh, kl, CE, CS, CS, 64, 0.125f, nullptr,
           nullptr, nullptr, sc, nullptr, nullptr, CS, 0,
           CB * CH, CH, SE, 64, SE, 64, (long long)CH * SS, SS);

    // softmax / adjacency -> combined [wk | wm]
    {
        dim3 g(CS, CB);
        softmax_kernel<<<g, 256>>>();
    }

    // msg+att = [wk|wm] @ [x;v]   (K = 4096, per batch); outF = ma
    run_mm(false, wh, wl, 2 * CS, xvh, xvl, CE, CS, CE, 2 * CS, 1.f, nullptr,
           nullptr, ma, nullptr, nullptr, nullptr, CE, 0,
           CB, 1, (long long)CS * 2 * CS, 0, (long long)2 * CS * CE, 0, SE, 0);

    // t1 = gelu(x @ Wm1'^T + bm1eff)
    run_mm(true, xh, xl, CE, Wh + 3 * WN, Wl + 3 * WN, CE, CBS, CE, CE, 1.f, b1e,
           nullptr, nullptr, nullptr, t1h, t1l, CE, 1, 1, 1, 0, 0, 0, 0, 0, 0);

    // t2 = t1 @ Wm2^T + bm2 + (msg+att)
    run_mm(true, t1h, t1l, CE, Wh + 4 * WN, Wl + 4 * WN, CE, CBS, CE, CE, 1.f, bm2,
           ma, nullptr, nullptr, t2h, t2l, CE, 0, 1, 1, 0, 0, 0, 0, 0, 0);

    // out = t2 @ Wo^T + bo; outF = out
    run_mm(true, t2h, t2l, CE, Wh + 5 * WN, Wl + 5 * WN, CE, CBS, CE, CE, 1.f, bo,
           nullptr, out, nullptr, nullptr, nullptr, CE, 0, 1, 1, 0, 0, 0, 0, 0, 0);
}

// round 12
// speedup vs baseline: 1.5336x; 1.2377x over previous
#include <cuda_runtime.h>
#include <cuda_fp16.h>
#include <cstdint>
#include <math.h>

constexpr int CB = 2, CS = 2048, CE = 512, CH = 8, CBS = CB * CS;

// ---------------- scratch (device globals; allocation-free) ----------------
__device__ __align__(128) __half g_scores[(size_t)CB * CH * CS * CS];  // 134 MB fp16
__device__ __align__(128) __half g_xh[CBS * CE], g_xl[CBS * CE];
__device__ __align__(128) __half g_qh[CBS * CE], g_ql[CBS * CE];
__device__ __align__(128) __half g_kh[CBS * CE];                        // B-only (hi)
// stacked [x ; v] per batch (B-only, hi): [b][0..2047]=x, [b][2048..4095]=v
__device__ __align__(128) __half g_xvh[(size_t)CB * 2 * CS * CE];
__device__ __align__(128) __half g_t1h[CBS * CE], g_t1l[CBS * CE];
__device__ __align__(128) __half g_t2h[CBS * CE], g_t2l[CBS * CE];
// combined A-operand weights [b][i][0..2047]=wk, [b][i][2048..4095]=wm (hi+lo)
__device__ __align__(128) __half g_wh[(size_t)CB * CS * 2 * CS], g_wl[(size_t)CB * CS * 2 * CS];
__device__ __align__(128) __half g_Wh[6 * CE * CE];                     // B-only (hi)
__device__ __align__(128) float g_msgatt[CBS * CE], g_bm1eff[CE];

// ---------------- low-level helpers ----------------
__device__ __forceinline__ uint32_t smem_u32(const void* p) {
    uint32_t a;
    asm("{ .reg .u64 t; cvta.to.shared.u64 t, %1; cvt.u32.u64 %0, t; }" : "=r"(a) : "l"(p));
    return a;
}
__device__ __forceinline__ void cpasync16(uint32_t dst, const void* src) {
    asm volatile("cp.async.ca.shared.global [%0], [%1], 16;" :: "r"(dst), "l"(src));
}
__device__ __forceinline__ void cpcommit() { asm volatile("cp.async.commit_group;"); }
template <int N> __device__ __forceinline__ void cpwait() {
    asm volatile("cp.async.wait_group %0;" :: "n"(N));
}
__device__ __forceinline__ void ldsm4(uint32_t* r, uint32_t a) {
    asm volatile("ldmatrix.sync.aligned.m8n8.x4.shared.b16 {%0,%1,%2,%3}, [%4];"
                 : "=r"(r[0]), "=r"(r[1]), "=r"(r[2]), "=r"(r[3]) : "r"(a));
}
__device__ __forceinline__ void ldsm4t(uint32_t* r, uint32_t a) {
    asm volatile("ldmatrix.sync.aligned.m8n8.x4.trans.shared.b16 {%0,%1,%2,%3}, [%4];"
                 : "=r"(r[0]), "=r"(r[1]), "=r"(r[2]), "=r"(r[3]) : "r"(a));
}
__device__ __forceinline__ void mma16816(float* c, const uint32_t* a, const uint32_t* b) {
    asm volatile(
        "mma.sync.aligned.m16n8k16.row.col.f32.f16.f16.f32 "
        "{%0,%1,%2,%3}, {%4,%5,%6,%7}, {%8,%9}, {%0,%1,%2,%3};"
        : "+f"(c[0]), "+f"(c[1]), "+f"(c[2]), "+f"(c[3])
        : "r"(a[0]), "r"(a[1]), "r"(a[2]), "r"(a[3]), "r"(b[0]), "r"(b[1]));
}
__device__ __forceinline__ void split2(float v, __half& h, __half& l) {
    h = __float2half(v);
    l = __float2half(v - __half2float(h));
}

// ---------------- fp16-split tensor-core GEMM (2-pass: (Ah+Al) x Bh) ----------------
// C = alpha * A @ op(B) (+bias)(+add0)(gelu). A:[M][K] rm (hi+lo). TRANSB: B:[N][K] rm else [K][N] rm (hi only).
// CTA tile 64x128, K-chunk 32, 2-stage cp.async pipeline, 8 warps (2x4) of 32x32.
// Output row mapping: o = coff + (r>>11)*segA + segB + (r&2047)*ldc + c
struct MP {
    const __half *Ah, *Al, *Bh;
    int lda, ldb, K;
    float alpha;
    const float *bias, *add0;
    float* outF;
    __half* outHalf;
    __half *outHi, *outLo;
    int ldc, gelu, zdiv;
    long long sAz, sAw, sBz, sBw, sCz, sCw;
    long long segA, segB;
};

constexpr int STG_A = 6144;    // 64 rows x 48 halves x 2B
constexpr int STG_B = 12288;   // max(128x48, 32x136) halves x 2B
constexpr int STAGE = 2 * STG_A + STG_B;  // 24576
constexpr int SMEM_BYTES = 2 * STAGE;     // 49152

// A tile: 64 rows x 32 halves, row stride 48 halves (96B); 1 chunk/thread
__device__ __forceinline__ void load_a(uint32_t sbase, const __half* G, int ld,
                                       int rowBase, int k0, int tid) {
    int row = tid >> 2, kc = tid & 3;
    cpasync16(sbase + (uint32_t)(row * 48 + kc * 8) * 2,
              G + (size_t)(rowBase + row) * ld + k0 + kc * 8);
}
// B (TN) tile: 128 rows x 32 halves, row stride 48 halves; 2 chunks/thread
__device__ __forceinline__ void load_bt(uint32_t sbase, const __half* G, int ld,
                                        int colBase, int k0, int tid) {
#pragma unroll
    for (int i = 0; i < 2; i++) {
        int c = tid + i * 256;
        int row = c >> 2, kc = c & 3;
        cpasync16(sbase + (uint32_t)(row * 48 + kc * 8) * 2,
                  G + (size_t)(colBase + row) * ld + k0 + kc * 8);
    }
}
// B (NN) tile: 32 k-rows x 128 n-cols, row stride 136 halves (272B); 2 chunks/thread
__device__ __forceinline__ void load_bn(uint32_t sbase, const __half* G, int ld,
                                        int colBase, int k0, int tid) {
#pragma unroll
    for (int i = 0; i < 2; i++) {
        int c = tid + i * 256;
        int kr = c >> 4, nc = c & 15;
        cpasync16(sbase + (uint32_t)(kr * 136 + nc * 8) * 2,
                  G + (size_t)(k0 + kr) * ld + colBase + nc * 8);
    }
}

template <bool TRANSB>
__global__ void __launch_bounds__(256, 2) mma_gemm(MP p) {
    extern __shared__ char smem[];
    const uint32_t sb = smem_u32(smem);
    const int tid = threadIdx.x, lane = tid & 31, wid = tid >> 5;
    const int warpM = wid >> 2, warpN = wid & 3;
    const int z = blockIdx.z, zq = z / p.zdiv, zr = z - zq * p.zdiv;
    const __half* Ah = p.Ah + (size_t)zq * p.sAz + (size_t)zr * p.sAw;
    const __half* Al = p.Al + (size_t)zq * p.sAz + (size_t)zr * p.sAw;
    const __half* Bh = p.Bh + (size_t)zq * p.sBz + (size_t)zr * p.sBw;
    const size_t coff = (size_t)zq * p.sCz + (size_t)zr * p.sCw;
    const int rowBase = blockIdx.y * 64, colBase = blockIdx.x * 128;

    float acc[2][4][4];
#pragma unroll
    for (int i = 0; i < 2; i++)
#pragma unroll
        for (int j = 0; j < 4; j++)
#pragma unroll
            for (int q = 0; q < 4; q++) acc[i][j][q] = 0.f;

    const int nchunk = p.K >> 5;

    auto loadStage = [&](int s, int k0) {
        uint32_t base = sb + s * STAGE;
        load_a(base, Ah, p.lda, rowBase, k0, tid);
        load_a(base + STG_A, Al, p.lda, rowBase, k0, tid);
        if (TRANSB) load_bt(base + 2 * STG_A, Bh, p.ldb, colBase, k0, tid);
        else        load_bn(base + 2 * STG_A, Bh, p.ldb, colBase, k0, tid);
        cpcommit();
    };

    loadStage(0, 0);
    for (int c = 0; c < nchunk; c++) {
        const int s = c & 1;
        if (c + 1 < nchunk) { loadStage(s ^ 1, (c + 1) << 5); cpwait<1>(); }
        else cpwait<0>();
        __syncthreads();

        const uint32_t base = sb + s * STAGE;
        const uint32_t aH = base, aL = base + STG_A;
        const uint32_t bH = base + 2 * STG_A;
#pragma unroll
        for (int kk = 0; kk < 2; kk++) {
            uint32_t ah[2][4], al[2][4], bh[4][2];
            const int ac = kk * 16 + (lane >> 4) * 8;
            const int ar = warpM * 32 + (lane & 15);
#pragma unroll
            for (int i = 0; i < 2; i++) {
                uint32_t off = (uint32_t)((ar + i * 16) * 48 + ac) * 2;
                ldsm4(ah[i], aH + off);
                ldsm4(al[i], aL + off);
            }
            if (TRANSB) {
#pragma unroll
                for (int jj = 0; jj < 2; jj++) {
                    int br = warpN * 32 + jj * 16 + (lane & 15);
                    uint32_t off = (uint32_t)(br * 48 + ac) * 2;
                    uint32_t r[4];
                    ldsm4(r, bH + off);
                    bh[jj * 2][0] = r[0]; bh[jj * 2][1] = r[2];
                    bh[jj * 2 + 1][0] = r[1]; bh[jj * 2 + 1][1] = r[3];
                }
            } else {
#pragma unroll
                for (int jj = 0; jj < 2; jj++) {
                    int br = kk * 16 + (lane & 15);
                    int bc = warpN * 32 + jj * 16 + (lane >> 4) * 8;
                    uint32_t off = (uint32_t)(br * 136 + bc) * 2;
                    uint32_t r[4];
                    ldsm4t(r, bH + off);
                    bh[jj * 2][0] = r[0]; bh[jj * 2][1] = r[1];
                    bh[jj * 2 + 1][0] = r[2]; bh[jj * 2 + 1][1] = r[3];
                }
            }
#pragma unroll
            for (int i = 0; i < 2; i++)
#pragma unroll
                for (int j = 0; j < 4; j++) {
                    mma16816(acc[i][j], ah[i], bh[j]);
                    mma16816(acc[i][j], al[i], bh[j]);
                }
        }
        __syncthreads();
    }

    // epilogue
    const float alpha = p.alpha;
#pragma unroll
    for (int i = 0; i < 2; i++) {
#pragma unroll
        for (int j = 0; j < 4; j++) {
            const int c0 = colBase + warpN * 32 + j * 8 + (lane & 3) * 2;
#pragma unroll
            for (int half = 0; half < 2; half++) {
                const int r = rowBase + warpM * 32 + i * 16 + (lane >> 2) + half * 8;
                float v0 = acc[i][j][half * 2] * alpha;
                float v1 = acc[i][j][half * 2 + 1] * alpha;
                if (p.bias) { v0 += p.bias[c0]; v1 += p.bias[c0 + 1]; }
                const size_t o = coff + (size_t)(r >> 11) * p.segA + p.segB
                               + (size_t)(r & 2047) * p.ldc + c0;
                if (p.add0) { v0 += p.add0[o]; v1 += p.add0[o + 1]; }
                if (p.gelu) {
                    v0 = 0.5f * v0 * (1.0f + erff(v0 * 0.70710678118654752440f));
                    v1 = 0.5f * v1 * (1.0f + erff(v1 * 0.70710678118654752440f));
                }
                if (p.outF) { float2 f2 = make_float2(v0, v1); *(float2*)(p.outF + o) = f2; }
                if (p.outHalf) {
                    __half2 hp; hp.x = __float2half(v0); hp.y = __float2half(v1);
                    *(__half2*)(p.outHalf + o) = hp;
                }
                if (p.outHi) {
                    __half h0 = __float2half(v0), h1 = __float2half(v1);
                    __half2 hh; hh.x = h0; hh.y = h1;
                    *(__half2*)(p.outHi + o) = hh;
                    if (p.outLo) {
                        __half2 ll;
                        ll.x = __float2half(v0 - __half2float(h0));
                        ll.y = __float2half(v1 - __half2float(h1));
                        *(__half2*)(p.outLo + o) = ll;
                    }
                }
            }
        }
    }
}

// ---------------- softmax + head-mean + adjacency ----------------
__device__ __forceinline__ float blockMax256(float v, float* red) {
#pragma unroll
    for (int o = 16; o; o >>= 1) v = fmaxf(v, __shfl_xor_sync(0xffffffffu, v, o));
    if ((threadIdx.x & 31) == 0) red[threadIdx.x >> 5] = v;
    __syncthreads();
    if (threadIdx.x < 32) {
        float x = (threadIdx.x < 8) ? red[threadIdx.x] : -3.4e38f;
#pragma unroll
        for (int o = 4; o; o >>= 1) x = fmaxf(x, __shfl_xor_sync(0xffffffffu, x, o));
        if (threadIdx.x == 0) red[0] = x;
    }
    __syncthreads();
    float r = red[0];
    __syncthreads();
    return r;
}
__device__ __forceinline__ float blockSum256(float v, float* red) {
#pragma unroll
    for (int o = 16; o; o >>= 1) v += __shfl_xor_sync(0xffffffffu, v, o);
    if ((threadIdx.x & 31) == 0) red[threadIdx.x >> 5] = v;
    __syncthreads();
    if (threadIdx.x < 32) {
        float x = (threadIdx.x < 8) ? red[threadIdx.x] : 0.f;
#pragma unroll
        for (int o = 4; o; o >>= 1) x += __shfl_xor_sync(0xffffffffu, x, o);
        if (threadIdx.x == 0) red[0] = x;
    }
    __syncthreads();
    float r = red[0];
    __syncthreads();
    return r;
}

// scores are fp16; reads/writes vectorized by pairs (j = 2*jp, 2*jp+1)
__global__ void __launch_bounds__(256) softmax_kernel() {
    const int i = blockIdx.x, b = blockIdx.y, tid = threadIdx.x;
    __shared__ float red[8];
    float wa[8];
#pragma unroll
    for (int u = 0; u < 8; u++) wa[u] = 0.f;
    for (int h = 0; h < CH; h++) {
        const __half2* row = (const __half2*)(g_scores + (((size_t)(b * CH + h) * CS) + i) * CS);
        float vals[8];
        float lmax = -3.4e38f;
#pragma unroll
        for (int u = 0; u < 4; u++) {
            __half2 pr = row[tid + 256 * u];
            float a0 = __half2float(pr.x), a1 = __half2float(pr.y);
            vals[2 * u] = a0; vals[2 * u + 1] = a1;
            lmax = fmaxf(lmax, fmaxf(a0, a1));
        }
        float m = blockMax256(lmax, red);
        float lsum = 0.f;
#pragma unroll
        for (int u = 0; u < 8; u++) { vals[u] = expf(vals[u] - m); lsum += vals[u]; }
        float inv = 1.0f / blockSum256(lsum, red);
#pragma unroll
        for (int u = 0; u < 8; u++) wa[u] += vals[u] * inv;
    }
    float cnt = 0.f;
#pragma unroll
    for (int u = 0; u < 8; u++) {
        float wm = wa[u] * (1.0f / CH);
        wa[u] = wm;
        cnt += (wm > 0.1f) ? 1.f : 0.f;
    }
    float nn = fmaxf(blockSum256(cnt, red), 1.0f);
    float invn = 1.0f / nn;
    // combined A row: [wk(0..2047) | wm(2048..4095)], paired stores
    size_t base = ((size_t)b * CS + i) * (size_t)(2 * CS);
#pragma unroll
    for (int u = 0; u < 4; u++) {
        int jp = tid + 256 * u;  // pair index, elements 2jp, 2jp+1
        float wm0 = wa[2 * u], wm1 = wa[2 * u + 1];
        float wk0 = (wm0 > 0.1f) ? wm0 * invn : 0.f;
        float wk1 = (wm1 > 0.1f) ? wm1 * invn : 0.f;
        __half h0, l0, h1, l1;
        split2(wk0, h0, l0); split2(wk1, h1, l1);
        __half2 hh, ll;
        hh.x = h0; hh.y = h1; ll.x = l0; ll.y = l1;
        *(__half2*)(g_wh + base + 2 * jp) = hh;
        *(__half2*)(g_wl + base + 2 * jp) = ll;
        split2(wm0, h0, l0); split2(wm1, h1, l1);
        hh.x = h0; hh.y = h1; ll.x = l0; ll.y = l1;
        *(__half2*)(g_wh + base + 2048 + 2 * jp) = hh;
        *(__half2*)(g_wl + base + 2048 + 2 * jp) = ll;
    }
}

// ---------------- prep kernels ----------------
__global__ void xsplit_kernel(const float* __restrict__ x) {
    int idx = blockIdx.x * 256 + threadIdx.x;
    if (idx < CBS * CE) {
        __half h, l;
        split2(x[idx], h, l);
        g_xh[idx] = h; g_xl[idx] = l;
        int b = idx >> 20;                 // CS*CE = 2^20
        int within = idx & ((CS * CE) - 1);
        g_xvh[(size_t)b * (2 * CS * CE) + within] = h;
    }
}
__global__ void wconv_kernel(const float* __restrict__ src, int ldin,
                             __half* __restrict__ dh) {
    int idx = blockIdx.x * 256 + threadIdx.x;
    if (idx < CE * CE) {
        int r = idx >> 9, c = idx & 511;
        dh[idx] = __float2half(src[(size_t)r * ldin + c]);
    }
}
__global__ void bm1eff_kernel(const float* __restrict__ Wm1, const float* __restrict__ bm1) {
    int e = blockIdx.x * 256 + threadIdx.x;
    if (e < CE) {
        float s = 0.f;
#pragma unroll
        for (int c = 0; c < CH; c++) s += Wm1[(size_t)e * (CE + CH) + CE + c];
        g_bm1eff[e] = bm1[e] + s * (1.0f / CS);
    }
}

// ---------------- host ----------------
static void run_mm(bool transb,
                   const __half* Ah, const __half* Al, int lda,
                   const __half* Bh, int ldb,
                   int M, int N, int K, float alpha,
                   const float* bias, const float* add0,
                   float* outF, __half* outHalf,
                   __half* outHi, __half* outLo,
                   int ldc, int gelu, int zcount, int zdiv,
                   long long sAz, long long sAw, long long sBz, long long sBw,
                   long long sCz, long long sCw,
                   long long segA = -1, long long segB = 0) {
    MP p;
    p.Ah = Ah; p.Al = Al; p.Bh = Bh;
    p.lda = lda; p.ldb = ldb; p.K = K; p.alpha = alpha;
    p.bias = bias; p.add0 = add0;
    p.outF = outF; p.outHalf = outHalf; p.outHi = outHi; p.outLo = outLo;
    p.ldc = ldc; p.gelu = gelu; p.zdiv = zdiv;
    p.sAz = sAz; p.sAw = sAw; p.sBz = sBz; p.sBw = sBw; p.sCz = sCz; p.sCw = sCw;
    p.segA = (segA < 0) ? (long long)2048 * ldc : segA;
    p.segB = segB;
    dim3 grid(N / 128, M / 64, zcount);
    if (transb) mma_gemm<true><<<grid, 256, SMEM_BYTES>>>(p);
    else        mma_gemm<false><<<grid, 256, SMEM_BYTES>>>(p);
}

extern "C" void kernel_launch(void* const* d_in, const int* in_sizes, int n_in,
                              void* d_out, int out_size) {
    const float* x   = (const float*)d_in[0];
    const float* Wq  = (const float*)d_in[1];
    const float* bq  = (const float*)d_in[2];
    const float* Wk  = (const float*)d_in[3];
    const float* bk  = (const float*)d_in[4];
    const float* Wv  = (const float*)d_in[5];
    const float* bv  = (const float*)d_in[6];
    const float* Wm1 = (const float*)d_in[7];
    const float* bm1 = (const float*)d_in[8];
    const float* Wm2 = (const float*)d_in[9];
    const float* bm2 = (const float*)d_in[10];
    const float* Wo  = (const float*)d_in[11];
    const float* bo  = (const float*)d_in[12];
    float* out = (float*)d_out;

    cudaFuncSetAttribute(mma_gemm<true>,  cudaFuncAttributeMaxDynamicSharedMemorySize, SMEM_BYTES);
    cudaFuncSetAttribute(mma_gemm<false>, cudaFuncAttributeMaxDynamicSharedMemorySize, SMEM_BYTES);

    float *ma, *b1e;
    __half *sc, *xh, *xl, *qh, *ql, *kh, *xvh;
    __half *t1h, *t1l, *t2h, *t2l, *wh, *wl, *Wh;
    cudaGetSymbolAddress((void**)&sc, g_scores);
    cudaGetSymbolAddress((void**)&ma, g_msgatt);
    cudaGetSymbolAddress((void**)&b1e, g_bm1eff);
    cudaGetSymbolAddress((void**)&xh, g_xh);   cudaGetSymbolAddress((void**)&xl, g_xl);
    cudaGetSymbolAddress((void**)&qh, g_qh);   cudaGetSymbolAddress((void**)&ql, g_ql);
    cudaGetSymbolAddress((void**)&kh, g_kh);
    cudaGetSymbolAddress((void**)&xvh, g_xvh);
    cudaGetSymbolAddress((void**)&t1h, g_t1h); cudaGetSymbolAddress((void**)&t1l, g_t1l);
    cudaGetSymbolAddress((void**)&t2h, g_t2h); cudaGetSymbolAddress((void**)&t2l, g_t2l);
    cudaGetSymbolAddress((void**)&wh, g_wh);   cudaGetSymbolAddress((void**)&wl, g_wl);
    cudaGetSymbolAddress((void**)&Wh, g_Wh);

    const long long SE = (long long)CS * CE;
    const long long SS = (long long)CS * CS;
    const int WN = CE * CE;

    // prep: splits + effective bm1
    xsplit_kernel<<<(CBS * CE + 255) / 256, 256>>>(x);
    int wgrid = (CE * CE + 255) / 256;
    wconv_kernel<<<wgrid, 256>>>(Wq, CE, Wh + 0 * WN);
    wconv_kernel<<<wgrid, 256>>>(Wk, CE, Wh + 1 * WN);
    wconv_kernel<<<wgrid, 256>>>(Wv, CE, Wh + 2 * WN);
    wconv_kernel<<<wgrid, 256>>>(Wm1, CE + CH, Wh + 3 * WN);
    wconv_kernel<<<wgrid, 256>>>(Wm2, CE, Wh + 4 * WN);
    wconv_kernel<<<wgrid, 256>>>(Wo, CE, Wh + 5 * WN);
    bm1eff_kernel<<<2, 256>>>(Wm1, bm1);

    // q (hi+lo), k (hi only), v -> stacked [x;v] (hi only, segment 1)
    run_mm(true, xh, xl, CE, Wh + 0 * WN, CE, CBS, CE, CE, 1.f, bq,
           nullptr, nullptr, nullptr, qh, ql, CE, 0, 1, 1, 0, 0, 0, 0, 0, 0);
    run_mm(true, xh, xl, CE, Wh + 1 * WN, CE, CBS, CE, CE, 1.f, bk,
           nullptr, nullptr, nullptr, kh, nullptr, CE, 0, 1, 1, 0, 0, 0, 0, 0, 0);
    run_mm(true, xh, xl, CE, Wh + 2 * WN, CE, CBS, CE, CE, 1.f, bv,
           nullptr, nullptr, nullptr, xvh, nullptr, CE, 0, 1, 1, 0, 0, 0, 0, 0, 0,
           (long long)2 * CS * CE /*segA: batch block*/, (long long)CS * CE /*segB: v segment*/);

    // scores (fp16) = 0.125 * q_h @ k_h^T  (z = b*8 + h)
    run_mm(true, qh, ql, CE, kh, CE, CS, CS, 64, 0.125f, nullptr,
           nullptr, nullptr, sc, nullptr, nullptr, CS, 0,
           CB * CH, CH, SE, 64, SE, 64, (long long)CH * SS, SS);

    // softmax / adjacency -> combined [wk | wm] (hi+lo)
    {
        dim3 g(CS, CB);
        softmax_kernel<<<g, 256>>>();
    }

    // msg+att = [wk|wm] @ [x;v]   (K = 4096, per batch); outF = ma
    run_mm(false, wh, wl, 2 * CS, xvh, CE, CS, CE, 2 * CS, 1.f, nullptr,
           nullptr, ma, nullptr, nullptr, nullptr, CE, 0,
           CB, 1, (long long)CS * 2 * CS, 0, (long long)2 * CS * CE, 0, SE, 0);

    // t1 = gelu(x @ Wm1'^T + bm1eff)
    run_mm(true, xh, xl, CE, Wh + 3 * WN, CE, CBS, CE, CE, 1.f, b1e,
           nullptr, nullptr, nullptr, t1h, t1l, CE, 1, 1, 1, 0, 0, 0, 0, 0, 0);

    // t2 = t1 @ Wm2^T + bm2 + (msg+att)
    run_mm(true, t1h, t1l, CE, Wh + 4 * WN, CE, CBS, CE, CE, 1.f, bm2,
           ma, nullptr, nullptr, t2h, t2l, CE, 0, 1, 1, 0, 0, 0, 0, 0, 0);

    // out = t2 @ Wo^T + bo; outF = out
    run_mm(true, t2h, t2l, CE, Wh + 5 * WN, CE, CBS, CE, CE, 1.f, bo,
           nullptr, out, nullptr, nullptr, nullptr, CE, 0, 1, 1, 0, 0, 0, 0, 0, 0);
}

// round 13
// speedup vs baseline: 1.8973x; 1.2372x over previous
#include <cuda_runtime.h>
#include <cuda_fp16.h>
#include <cstdint>
#include <math.h>

constexpr int CB = 2, CS = 2048, CE = 512, CH = 8, CBS = CB * CS;

// ---------------- scratch (device globals; allocation-free) ----------------
__device__ __align__(128) __half g_scores[(size_t)CB * CH * CS * CS];  // 134 MB fp16
__device__ __align__(128) __half g_xh[CBS * CE], g_xl[CBS * CE];
__device__ __align__(128) __half g_qh[CBS * CE];                        // hi-only (scores 1-pass)
__device__ __align__(128) __half g_kh[CBS * CE];                        // B-only (hi)
// stacked [x ; v] per batch (B-only, hi): [b][0..2047]=x, [b][2048..4095]=v
__device__ __align__(128) __half g_xvh[(size_t)CB * 2 * CS * CE];
__device__ __align__(128) __half g_t1h[CBS * CE], g_t1l[CBS * CE];
__device__ __align__(128) __half g_t2h[CBS * CE], g_t2l[CBS * CE];
// combined A-operand weights [b][i][0..2047]=wk, [b][i][2048..4095]=wm (hi-only, msg+att 1-pass)
__device__ __align__(128) __half g_wh[(size_t)CB * CS * 2 * CS];
__device__ __align__(128) __half g_Wh[6 * CE * CE];                     // B-only (hi)
__device__ __align__(128) float g_msgatt[CBS * CE], g_bm1eff[CE];

// ---------------- low-level helpers ----------------
__device__ __forceinline__ uint32_t smem_u32(const void* p) {
    uint32_t a;
    asm("{ .reg .u64 t; cvta.to.shared.u64 t, %1; cvt.u32.u64 %0, t; }" : "=r"(a) : "l"(p));
    return a;
}
__device__ __forceinline__ void cpasync16(uint32_t dst, const void* src) {
    asm volatile("cp.async.ca.shared.global [%0], [%1], 16;" :: "r"(dst), "l"(src));
}
__device__ __forceinline__ void cpcommit() { asm volatile("cp.async.commit_group;"); }
template <int N> __device__ __forceinline__ void cpwait() {
    asm volatile("cp.async.wait_group %0;" :: "n"(N));
}
__device__ __forceinline__ void ldsm4(uint32_t* r, uint32_t a) {
    asm volatile("ldmatrix.sync.aligned.m8n8.x4.shared.b16 {%0,%1,%2,%3}, [%4];"
                 : "=r"(r[0]), "=r"(r[1]), "=r"(r[2]), "=r"(r[3]) : "r"(a));
}
__device__ __forceinline__ void ldsm4t(uint32_t* r, uint32_t a) {
    asm volatile("ldmatrix.sync.aligned.m8n8.x4.trans.shared.b16 {%0,%1,%2,%3}, [%4];"
                 : "=r"(r[0]), "=r"(r[1]), "=r"(r[2]), "=r"(r[3]) : "r"(a));
}
__device__ __forceinline__ void mma16816(float* c, const uint32_t* a, const uint32_t* b) {
    asm volatile(
        "mma.sync.aligned.m16n8k16.row.col.f32.f16.f16.f32 "
        "{%0,%1,%2,%3}, {%4,%5,%6,%7}, {%8,%9}, {%0,%1,%2,%3};"
        : "+f"(c[0]), "+f"(c[1]), "+f"(c[2]), "+f"(c[3])
        : "r"(a[0]), "r"(a[1]), "r"(a[2]), "r"(a[3]), "r"(b[0]), "r"(b[1]));
}
__device__ __forceinline__ void split2(float v, __half& h, __half& l) {
    h = __float2half(v);
    l = __float2half(v - __half2float(h));
}

// ---------------- fp16-split tensor-core GEMM ----------------
// TWOPASS: C = alpha*(Ah+Al)@op(Bh); else C = alpha*Ah@op(Bh). (+bias)(+add0)(gelu)
// A:[M][K] rm. TRANSB: B:[N][K] rm else [K][N] rm (hi only).
// CTA tile 64x128, K-chunk 32, 2-stage cp.async pipeline, 8 warps (2x4) of 32x32.
// Output row mapping: o = coff + (r>>11)*segA + segB + (r&2047)*ldc + c
struct MP {
    const __half *Ah, *Al, *Bh;
    int lda, ldb, K;
    float alpha;
    const float *bias, *add0;
    float* outF;
    __half* outHalf;
    __half *outHi, *outLo;
    int ldc, gelu, zdiv;
    long long sAz, sAw, sBz, sBw, sCz, sCw;
    long long segA, segB;
};

constexpr int STG_A = 6144;    // 64 rows x 48 halves x 2B
constexpr int STG_B = 12288;   // max(128x48, 32x136) halves x 2B
constexpr int STAGE = 2 * STG_A + STG_B;  // 24576
constexpr int SMEM_BYTES = 2 * STAGE;     // 49152

// A tile: 64 rows x 32 halves, row stride 48 halves (96B); 1 chunk/thread
__device__ __forceinline__ void load_a(uint32_t sbase, const __half* G, int ld,
                                       int rowBase, int k0, int tid) {
    int row = tid >> 2, kc = tid & 3;
    cpasync16(sbase + (uint32_t)(row * 48 + kc * 8) * 2,
              G + (size_t)(rowBase + row) * ld + k0 + kc * 8);
}
// B (TN) tile: 128 rows x 32 halves, row stride 48 halves; 2 chunks/thread
__device__ __forceinline__ void load_bt(uint32_t sbase, const __half* G, int ld,
                                        int colBase, int k0, int tid) {
#pragma unroll
    for (int i = 0; i < 2; i++) {
        int c = tid + i * 256;
        int row = c >> 2, kc = c & 3;
        cpasync16(sbase + (uint32_t)(row * 48 + kc * 8) * 2,
                  G + (size_t)(colBase + row) * ld + k0 + kc * 8);
    }
}
// B (NN) tile: 32 k-rows x 128 n-cols, row stride 136 halves (272B); 2 chunks/thread
__device__ __forceinline__ void load_bn(uint32_t sbase, const __half* G, int ld,
                                        int colBase, int k0, int tid) {
#pragma unroll
    for (int i = 0; i < 2; i++) {
        int c = tid + i * 256;
        int kr = c >> 4, nc = c & 15;
        cpasync16(sbase + (uint32_t)(kr * 136 + nc * 8) * 2,
                  G + (size_t)(k0 + kr) * ld + colBase + nc * 8);
    }
}

template <bool TRANSB, bool TWOPASS>
__global__ void __launch_bounds__(256, 2) mma_gemm(MP p) {
    extern __shared__ char smem[];
    const uint32_t sb = smem_u32(smem);
    const int tid = threadIdx.x, lane = tid & 31, wid = tid >> 5;
    const int warpM = wid >> 2, warpN = wid & 3;
    const int z = blockIdx.z, zq = z / p.zdiv, zr = z - zq * p.zdiv;
    const __half* Ah = p.Ah + (size_t)zq * p.sAz + (size_t)zr * p.sAw;
    const __half* Al = TWOPASS ? p.Al + (size_t)zq * p.sAz + (size_t)zr * p.sAw : nullptr;
    const __half* Bh = p.Bh + (size_t)zq * p.sBz + (size_t)zr * p.sBw;
    const size_t coff = (size_t)zq * p.sCz + (size_t)zr * p.sCw;
    const int rowBase = blockIdx.y * 64, colBase = blockIdx.x * 128;

    float acc[2][4][4];
#pragma unroll
    for (int i = 0; i < 2; i++)
#pragma unroll
        for (int j = 0; j < 4; j++)
#pragma unroll
            for (int q = 0; q < 4; q++) acc[i][j][q] = 0.f;

    const int nchunk = p.K >> 5;

    auto loadStage = [&](int s, int k0) {
        uint32_t base = sb + s * STAGE;
        load_a(base, Ah, p.lda, rowBase, k0, tid);
        if (TWOPASS) load_a(base + STG_A, Al, p.lda, rowBase, k0, tid);
        if (TRANSB) load_bt(base + 2 * STG_A, Bh, p.ldb, colBase, k0, tid);
        else        load_bn(base + 2 * STG_A, Bh, p.ldb, colBase, k0, tid);
        cpcommit();
    };

    loadStage(0, 0);
    for (int c = 0; c < nchunk; c++) {
        const int s = c & 1;
        if (c + 1 < nchunk) { loadStage(s ^ 1, (c + 1) << 5); cpwait<1>(); }
        else cpwait<0>();
        __syncthreads();

        const uint32_t base = sb + s * STAGE;
        const uint32_t aH = base, aL = base + STG_A;
        const uint32_t bH = base + 2 * STG_A;
#pragma unroll
        for (int kk = 0; kk < 2; kk++) {
            uint32_t ah[2][4], al[2][4], bh[4][2];
            const int ac = kk * 16 + (lane >> 4) * 8;
            const int ar = warpM * 32 + (lane & 15);
#pragma unroll
            for (int i = 0; i < 2; i++) {
                uint32_t off = (uint32_t)((ar + i * 16) * 48 + ac) * 2;
                ldsm4(ah[i], aH + off);
                if (TWOPASS) ldsm4(al[i], aL + off);
            }
            if (TRANSB) {
#pragma unroll
                for (int jj = 0; jj < 2; jj++) {
                    int br = warpN * 32 + jj * 16 + (lane & 15);
                    uint32_t off = (uint32_t)(br * 48 + ac) * 2;
                    uint32_t r[4];
                    ldsm4(r, bH + off);
                    bh[jj * 2][0] = r[0]; bh[jj * 2][1] = r[2];
                    bh[jj * 2 + 1][0] = r[1]; bh[jj * 2 + 1][1] = r[3];
                }
            } else {
#pragma unroll
                for (int jj = 0; jj < 2; jj++) {
                    int br = kk * 16 + (lane & 15);
                    int bc = warpN * 32 + jj * 16 + (lane >> 4) * 8;
                    uint32_t off = (uint32_t)(br * 136 + bc) * 2;
                    uint32_t r[4];
                    ldsm4t(r, bH + off);
                    bh[jj * 2][0] = r[0]; bh[jj * 2][1] = r[1];
                    bh[jj * 2 + 1][0] = r[2]; bh[jj * 2 + 1][1] = r[3];
                }
            }
#pragma unroll
            for (int i = 0; i < 2; i++)
#pragma unroll
                for (int j = 0; j < 4; j++) {
                    mma16816(acc[i][j], ah[i], bh[j]);
                    if (TWOPASS) mma16816(acc[i][j], al[i], bh[j]);
                }
        }
        __syncthreads();
    }

    // epilogue
    const float alpha = p.alpha;
#pragma unroll
    for (int i = 0; i < 2; i++) {
#pragma unroll
        for (int j = 0; j < 4; j++) {
            const int c0 = colBase + warpN * 32 + j * 8 + (lane & 3) * 2;
#pragma unroll
            for (int half = 0; half < 2; half++) {
                const int r = rowBase + warpM * 32 + i * 16 + (lane >> 2) + half * 8;
                float v0 = acc[i][j][half * 2] * alpha;
                float v1 = acc[i][j][half * 2 + 1] * alpha;
                if (p.bias) { v0 += p.bias[c0]; v1 += p.bias[c0 + 1]; }
                const size_t o = coff + (size_t)(r >> 11) * p.segA + p.segB
                               + (size_t)(r & 2047) * p.ldc + c0;
                if (p.add0) { v0 += p.add0[o]; v1 += p.add0[o + 1]; }
                if (p.gelu) {
                    v0 = 0.5f * v0 * (1.0f + erff(v0 * 0.70710678118654752440f));
                    v1 = 0.5f * v1 * (1.0f + erff(v1 * 0.70710678118654752440f));
                }
                if (p.outF) { float2 f2 = make_float2(v0, v1); *(float2*)(p.outF + o) = f2; }
                if (p.outHalf) {
                    __half2 hp; hp.x = __float2half(v0); hp.y = __float2half(v1);
                    *(__half2*)(p.outHalf + o) = hp;
                }
                if (p.outHi) {
                    __half h0 = __float2half(v0), h1 = __float2half(v1);
                    __half2 hh; hh.x = h0; hh.y = h1;
                    *(__half2*)(p.outHi + o) = hh;
                    if (p.outLo) {
                        __half2 ll;
                        ll.x = __float2half(v0 - __half2float(h0));
                        ll.y = __float2half(v1 - __half2float(h1));
                        *(__half2*)(p.outLo + o) = ll;
                    }
                }
            }
        }
    }
}

// ---------------- softmax + head-mean + adjacency ----------------
__device__ __forceinline__ float blockMax256(float v, float* red) {
#pragma unroll
    for (int o = 16; o; o >>= 1) v = fmaxf(v, __shfl_xor_sync(0xffffffffu, v, o));
    if ((threadIdx.x & 31) == 0) red[threadIdx.x >> 5] = v;
    __syncthreads();
    if (threadIdx.x < 32) {
        float x = (threadIdx.x < 8) ? red[threadIdx.x] : -3.4e38f;
#pragma unroll
        for (int o = 4; o; o >>= 1) x = fmaxf(x, __shfl_xor_sync(0xffffffffu, x, o));
        if (threadIdx.x == 0) red[0] = x;
    }
    __syncthreads();
    float r = red[0];
    __syncthreads();
    return r;
}
__device__ __forceinline__ float blockSum256(float v, float* red) {
#pragma unroll
    for (int o = 16; o; o >>= 1) v += __shfl_xor_sync(0xffffffffu, v, o);
    if ((threadIdx.x & 31) == 0) red[threadIdx.x >> 5] = v;
    __syncthreads();
    if (threadIdx.x < 32) {
        float x = (threadIdx.x < 8) ? red[threadIdx.x] : 0.f;
#pragma unroll
        for (int o = 4; o; o >>= 1) x += __shfl_xor_sync(0xffffffffu, x, o);
        if (threadIdx.x == 0) red[0] = x;
    }
    __syncthreads();
    float r = red[0];
    __syncthreads();
    return r;
}

// scores are fp16; reads/writes vectorized by pairs (j = 2*jp, 2*jp+1)
__global__ void __launch_bounds__(256) softmax_kernel() {
    const int i = blockIdx.x, b = blockIdx.y, tid = threadIdx.x;
    __shared__ float red[8];
    float wa[8];
#pragma unroll
    for (int u = 0; u < 8; u++) wa[u] = 0.f;
    for (int h = 0; h < CH; h++) {
        const __half2* row = (const __half2*)(g_scores + (((size_t)(b * CH + h) * CS) + i) * CS);
        float vals[8];
        float lmax = -3.4e38f;
#pragma unroll
        for (int u = 0; u < 4; u++) {
            __half2 pr = row[tid + 256 * u];
            float a0 = __half2float(pr.x), a1 = __half2float(pr.y);
            vals[2 * u] = a0; vals[2 * u + 1] = a1;
            lmax = fmaxf(lmax, fmaxf(a0, a1));
        }
        float m = blockMax256(lmax, red);
        float lsum = 0.f;
#pragma unroll
        for (int u = 0; u < 8; u++) { vals[u] = __expf(vals[u] - m); lsum += vals[u]; }
        float inv = 1.0f / blockSum256(lsum, red);
#pragma unroll
        for (int u = 0; u < 8; u++) wa[u] += vals[u] * inv;
    }
    float cnt = 0.f;
#pragma unroll
    for (int u = 0; u < 8; u++) {
        float wm = wa[u] * (1.0f / CH);
        wa[u] = wm;
        cnt += (wm > 0.1f) ? 1.f : 0.f;
    }
    float nn = fmaxf(blockSum256(cnt, red), 1.0f);
    float invn = 1.0f / nn;
    // combined A row: [wk(0..2047) | wm(2048..4095)], hi-only paired stores
    size_t base = ((size_t)b * CS + i) * (size_t)(2 * CS);
#pragma unroll
    for (int u = 0; u < 4; u++) {
        int jp = tid + 256 * u;  // pair index, elements 2jp, 2jp+1
        float wm0 = wa[2 * u], wm1 = wa[2 * u + 1];
        float wk0 = (wm0 > 0.1f) ? wm0 * invn : 0.f;
        float wk1 = (wm1 > 0.1f) ? wm1 * invn : 0.f;
        __half2 hh;
        hh.x = __float2half(wk0); hh.y = __float2half(wk1);
        *(__half2*)(g_wh + base + 2 * jp) = hh;
        hh.x = __float2half(wm0); hh.y = __float2half(wm1);
        *(__half2*)(g_wh + base + 2048 + 2 * jp) = hh;
    }
}

// ---------------- prep kernels ----------------
__global__ void xsplit_kernel(const float* __restrict__ x) {
    int idx = blockIdx.x * 256 + threadIdx.x;
    if (idx < CBS * CE) {
        __half h, l;
        split2(x[idx], h, l);
        g_xh[idx] = h; g_xl[idx] = l;
        int b = idx >> 20;                 // CS*CE = 2^20
        int within = idx & ((CS * CE) - 1);
        g_xvh[(size_t)b * (2 * CS * CE) + within] = h;
    }
}
__global__ void wconv_kernel(const float* __restrict__ src, int ldin,
                             __half* __restrict__ dh) {
    int idx = blockIdx.x * 256 + threadIdx.x;
    if (idx < CE * CE) {
        int r = idx >> 9, c = idx & 511;
        dh[idx] = __float2half(src[(size_t)r * ldin + c]);
    }
}
__global__ void bm1eff_kernel(const float* __restrict__ Wm1, const float* __restrict__ bm1) {
    int e = blockIdx.x * 256 + threadIdx.x;
    if (e < CE) {
        float s = 0.f;
#pragma unroll
        for (int c = 0; c < CH; c++) s += Wm1[(size_t)e * (CE + CH) + CE + c];
        g_bm1eff[e] = bm1[e] + s * (1.0f / CS);
    }
}

// ---------------- host ----------------
static void run_mm(bool transb,
                   const __half* Ah, const __half* Al, int lda,
                   const __half* Bh, int ldb,
                   int M, int N, int K, float alpha,
                   const float* bias, const float* add0,
                   float* outF, __half* outHalf,
                   __half* outHi, __half* outLo,
                   int ldc, int gelu, int zcount, int zdiv,
                   long long sAz, long long sAw, long long sBz, long long sBw,
                   long long sCz, long long sCw,
                   long long segA = -1, long long segB = 0) {
    MP p;
    p.Ah = Ah; p.Al = Al; p.Bh = Bh;
    p.lda = lda; p.ldb = ldb; p.K = K; p.alpha = alpha;
    p.bias = bias; p.add0 = add0;
    p.outF = outF; p.outHalf = outHalf; p.outHi = outHi; p.outLo = outLo;
    p.ldc = ldc; p.gelu = gelu; p.zdiv = zdiv;
    p.sAz = sAz; p.sAw = sAw; p.sBz = sBz; p.sBw = sBw; p.sCz = sCz; p.sCw = sCw;
    p.segA = (segA < 0) ? (long long)2048 * ldc : segA;
    p.segB = segB;
    dim3 grid(N / 128, M / 64, zcount);
    const bool twopass = (Al != nullptr);
    if (transb) {
        if (twopass) mma_gemm<true, true><<<grid, 256, SMEM_BYTES>>>(p);
        else         mma_gemm<true, false><<<grid, 256, SMEM_BYTES>>>(p);
    } else {
        if (twopass) mma_gemm<false, true><<<grid, 256, SMEM_BYTES>>>(p);
        else         mma_gemm<false, false><<<grid, 256, SMEM_BYTES>>>(p);
    }
}

extern "C" void kernel_launch(void* const* d_in, const int* in_sizes, int n_in,
                              void* d_out, int out_size) {
    const float* x   = (const float*)d_in[0];
    const float* Wq  = (const float*)d_in[1];
    const float* bq  = (const float*)d_in[2];
    const float* Wk  = (const float*)d_in[3];
    const float* bk  = (const float*)d_in[4];
    const float* Wv  = (const float*)d_in[5];
    const float* bv  = (const float*)d_in[6];
    const float* Wm1 = (const float*)d_in[7];
    const float* bm1 = (const float*)d_in[8];
    const float* Wm2 = (const float*)d_in[9];
    const float* bm2 = (const float*)d_in[10];
    const float* Wo  = (const float*)d_in[11];
    const float* bo  = (const float*)d_in[12];
    float* out = (float*)d_out;

    cudaFuncSetAttribute(mma_gemm<true, true>,   cudaFuncAttributeMaxDynamicSharedMemorySize, SMEM_BYTES);
    cudaFuncSetAttribute(mma_gemm<true, false>,  cudaFuncAttributeMaxDynamicSharedMemorySize, SMEM_BYTES);
    cudaFuncSetAttribute(mma_gemm<false, true>,  cudaFuncAttributeMaxDynamicSharedMemorySize, SMEM_BYTES);
    cudaFuncSetAttribute(mma_gemm<false, false>, cudaFuncAttributeMaxDynamicSharedMemorySize, SMEM_BYTES);

    float *ma, *b1e;
    __half *sc, *xh, *xl, *qh, *kh, *xvh;
    __half *t1h, *t1l, *t2h, *t2l, *wh, *Wh;
    cudaGetSymbolAddress((void**)&sc, g_scores);
    cudaGetSymbolAddress((void**)&ma, g_msgatt);
    cudaGetSymbolAddress((void**)&b1e, g_bm1eff);
    cudaGetSymbolAddress((void**)&xh, g_xh);   cudaGetSymbolAddress((void**)&xl, g_xl);
    cudaGetSymbolAddress((void**)&qh, g_qh);
    cudaGetSymbolAddress((void**)&kh, g_kh);
    cudaGetSymbolAddress((void**)&xvh, g_xvh);
    cudaGetSymbolAddress((void**)&t1h, g_t1h); cudaGetSymbolAddress((void**)&t1l, g_t1l);
    cudaGetSymbolAddress((void**)&t2h, g_t2h); cudaGetSymbolAddress((void**)&t2l, g_t2l);
    cudaGetSymbolAddress((void**)&wh, g_wh);
    cudaGetSymbolAddress((void**)&Wh, g_Wh);

    const long long SE = (long long)CS * CE;
    const long long SS = (long long)CS * CS;
    const int WN = CE * CE;

    // prep: splits + effective bm1
    xsplit_kernel<<<(CBS * CE + 255) / 256, 256>>>(x);
    int wgrid = (CE * CE + 255) / 256;
    wconv_kernel<<<wgrid, 256>>>(Wq, CE, Wh + 0 * WN);
    wconv_kernel<<<wgrid, 256>>>(Wk, CE, Wh + 1 * WN);
    wconv_kernel<<<wgrid, 256>>>(Wv, CE, Wh + 2 * WN);
    wconv_kernel<<<wgrid, 256>>>(Wm1, CE + CH, Wh + 3 * WN);
    wconv_kernel<<<wgrid, 256>>>(Wm2, CE, Wh + 4 * WN);
    wconv_kernel<<<wgrid, 256>>>(Wo, CE, Wh + 5 * WN);
    bm1eff_kernel<<<2, 256>>>(Wm1, bm1);

    // q (hi only, 2-pass A=x), k (hi only), v -> stacked [x;v] (hi only, segment 1)
    run_mm(true, xh, xl, CE, Wh + 0 * WN, CE, CBS, CE, CE, 1.f, bq,
           nullptr, nullptr, nullptr, qh, nullptr, CE, 0, 1, 1, 0, 0, 0, 0, 0, 0);
    run_mm(true, xh, xl, CE, Wh + 1 * WN, CE, CBS, CE, CE, 1.f, bk,
           nullptr, nullptr, nullptr, kh, nullptr, CE, 0, 1, 1, 0, 0, 0, 0, 0, 0);
    run_mm(true, xh, xl, CE, Wh + 2 * WN, CE, CBS, CE, CE, 1.f, bv,
           nullptr, nullptr, nullptr, xvh, nullptr, CE, 0, 1, 1, 0, 0, 0, 0, 0, 0,
           (long long)2 * CS * CE /*segA: batch block*/, (long long)CS * CE /*segB: v segment*/);

    // scores (fp16) = 0.125 * q_h @ k_h^T  (z = b*8 + h) -- 1-pass (Al = nullptr)
    run_mm(true, qh, nullptr, CE, kh, CE, CS, CS, 64, 0.125f, nullptr,
           nullptr, nullptr, sc, nullptr, nullptr, CS, 0,
           CB * CH, CH, SE, 64, SE, 64, (long long)CH * SS, SS);

    // softmax / adjacency -> combined [wk | wm] (hi only)
    {
        dim3 g(CS, CB);
        softmax_kernel<<<g, 256>>>();
    }

    // msg+att = [wk|wm] @ [x;v]   (K = 4096, per batch) -- 1-pass; outF = ma
    run_mm(false, wh, nullptr, 2 * CS, xvh, CE, CS, CE, 2 * CS, 1.f, nullptr,
           nullptr, ma, nullptr, nullptr, nullptr, CE, 0,
           CB, 1, (long long)CS * 2 * CS, 0, (long long)2 * CS * CE, 0, SE, 0);

    // t1 = gelu(x @ Wm1'^T + bm1eff)  (2-pass A=x)
    run_mm(true, xh, xl, CE, Wh + 3 * WN, CE, CBS, CE, CE, 1.f, b1e,
           nullptr, nullptr, nullptr, t1h, t1l, CE, 1, 1, 1, 0, 0, 0, 0, 0, 0);

    // t2 = t1 @ Wm2^T + bm2 + (msg+att)  (2-pass A=t1)
    run_mm(true, t1h, t1l, CE, Wh + 4 * WN, CE, CBS, CE, CE, 1.f, bm2,
           ma, nullptr, nullptr, t2h, t2l, CE, 0, 1, 1, 0, 0, 0, 0, 0, 0);

    // out = t2 @ Wo^T + bo  (2-pass A=t2); outF = out
    run_mm(true, t2h, t2l, CE, Wh + 5 * WN, CE, CBS, CE, CE, 1.f, bo,
           nullptr, out, nullptr, nullptr, nullptr, CE, 0, 1, 1, 0, 0, 0, 0, 0, 0);
}

// round 16
// speedup vs baseline: 2.0926x; 1.1029x over previous
#include <cuda_runtime.h>
#include <cuda_fp16.h>
#include <cstdint>
#include <math.h>

constexpr int CB = 2, CS = 2048, CE = 512, CH = 8, CBS = CB * CS;

// ---------------- scratch (device globals; allocation-free) ----------------
__device__ __align__(128) __half g_scores[(size_t)CB * CH * CS * CS];  // 134 MB fp16
__device__ __align__(128) __half g_xh[CBS * CE];                        // x hi-only
__device__ __align__(128) __half g_qh[CBS * CE];                        // hi-only
__device__ __align__(128) __half g_kh[CBS * CE];                        // hi-only
// stacked [x ; v] per batch (B-only, hi): [b][0..2047]=x, [b][2048..4095]=v
__device__ __align__(128) __half g_xvh[(size_t)CB * 2 * CS * CE];
__device__ __align__(128) __half g_t1h[CBS * CE], g_t1l[CBS * CE];
__device__ __align__(128) __half g_t2h[CBS * CE], g_t2l[CBS * CE];
// combined A-operand weights [b][i][0..2047]=wk, [b][i][2048..4095]=wm (hi-only)
__device__ __align__(128) __half g_wh[(size_t)CB * CS * 2 * CS];
__device__ __align__(128) __half g_Wh[6 * CE * CE];                     // hi-only
__device__ __align__(128) float g_msgatt[CBS * CE], g_bm1eff[CE];

// ---------------- low-level helpers ----------------
__device__ __forceinline__ uint32_t smem_u32(const void* p) {
    uint32_t a;
    asm("{ .reg .u64 t; cvta.to.shared.u64 t, %1; cvt.u32.u64 %0, t; }" : "=r"(a) : "l"(p));
    return a;
}
__device__ __forceinline__ void cpasync16(uint32_t dst, const void* src) {
    asm volatile("cp.async.ca.shared.global [%0], [%1], 16;" :: "r"(dst), "l"(src));
}
__device__ __forceinline__ void cpcommit() { asm volatile("cp.async.commit_group;"); }
template <int N> __device__ __forceinline__ void cpwait() {
    asm volatile("cp.async.wait_group %0;" :: "n"(N));
}
__device__ __forceinline__ void ldsm4(uint32_t* r, uint32_t a) {
    asm volatile("ldmatrix.sync.aligned.m8n8.x4.shared.b16 {%0,%1,%2,%3}, [%4];"
                 : "=r"(r[0]), "=r"(r[1]), "=r"(r[2]), "=r"(r[3]) : "r"(a));
}
__device__ __forceinline__ void ldsm4t(uint32_t* r, uint32_t a) {
    asm volatile("ldmatrix.sync.aligned.m8n8.x4.trans.shared.b16 {%0,%1,%2,%3}, [%4];"
                 : "=r"(r[0]), "=r"(r[1]), "=r"(r[2]), "=r"(r[3]) : "r"(a));
}
__device__ __forceinline__ void mma16816(float* c, const uint32_t* a, const uint32_t* b) {
    asm volatile(
        "mma.sync.aligned.m16n8k16.row.col.f32.f16.f16.f32 "
        "{%0,%1,%2,%3}, {%4,%5,%6,%7}, {%8,%9}, {%0,%1,%2,%3};"
        : "+f"(c[0]), "+f"(c[1]), "+f"(c[2]), "+f"(c[3])
        : "r"(a[0]), "r"(a[1]), "r"(a[2]), "r"(a[3]), "r"(b[0]), "r"(b[1]));
}
__device__ __forceinline__ void split2(float v, __half& h, __half& l) {
    h = __float2half(v);
    l = __float2half(v - __half2float(h));
}

// ---------------- fp16-split tensor-core GEMM ----------------
// TWOPASS: C = alpha*(Ah+Al)@op(Bh); else C = alpha*Ah@op(Bh). (+bias)(+add0)(gelu)
// A:[M][K] rm. TRANSB: B:[N][K] rm else [K][N] rm (hi only).
// CTA tile 64x128, K-chunk 32, 2-stage cp.async pipeline, 8 warps (2x4) of 32x32.
// Output row mapping: o = coff + (r>>11)*segA + segB + (r&2047)*ldc + c
struct MP {
    const __half *Ah, *Al, *Bh;
    int lda, ldb, K;
    float alpha;
    const float *bias, *add0;
    float* outF;
    __half* outHalf;
    __half *outHi, *outLo;
    int ldc, gelu, zdiv;
    long long sAz, sAw, sBz, sBw, sCz, sCw;
    long long segA, segB;
};

constexpr int STG_A = 6144;    // 64 rows x 48 halves x 2B
constexpr int STG_B = 12288;   // max(128x48, 32x136) halves x 2B
constexpr int STAGE = 2 * STG_A + STG_B;  // 24576
constexpr int SMEM_BYTES = 2 * STAGE;     // 49152

// A tile: 64 rows x 32 halves, row stride 48 halves (96B); 1 chunk/thread
__device__ __forceinline__ void load_a(uint32_t sbase, const __half* G, int ld,
                                       int rowBase, int k0, int tid) {
    int row = tid >> 2, kc = tid & 3;
    cpasync16(sbase + (uint32_t)(row * 48 + kc * 8) * 2,
              G + (size_t)(rowBase + row) * ld + k0 + kc * 8);
}
// B (TN) tile: 128 rows x 32 halves, row stride 48 halves; 2 chunks/thread
__device__ __forceinline__ void load_bt(uint32_t sbase, const __half* G, int ld,
                                        int colBase, int k0, int tid) {
#pragma unroll
    for (int i = 0; i < 2; i++) {
        int c = tid + i * 256;
        int row = c >> 2, kc = c & 3;
        cpasync16(sbase + (uint32_t)(row * 48 + kc * 8) * 2,
                  G + (size_t)(colBase + row) * ld + k0 + kc * 8);
    }
}
// B (NN) tile: 32 k-rows x 128 n-cols, row stride 136 halves (272B); 2 chunks/thread
__device__ __forceinline__ void load_bn(uint32_t sbase, const __half* G, int ld,
                                        int colBase, int k0, int tid) {
#pragma unroll
    for (int i = 0; i < 2; i++) {
        int c = tid + i * 256;
        int kr = c >> 4, nc = c & 15;
        cpasync16(sbase + (uint32_t)(kr * 136 + nc * 8) * 2,
                  G + (size_t)(k0 + kr) * ld + colBase + nc * 8);
    }
}

template <bool TRANSB, bool TWOPASS>
__global__ void __launch_bounds__(256, 2) mma_gemm(MP p) {
    extern __shared__ char smem[];
    const uint32_t sb = smem_u32(smem);
    const int tid = threadIdx.x, lane = tid & 31, wid = tid >> 5;
    const int warpM = wid >> 2, warpN = wid & 3;
    const int z = blockIdx.z, zq = z / p.zdiv, zr = z - zq * p.zdiv;
    const __half* Ah = p.Ah + (size_t)zq * p.sAz + (size_t)zr * p.sAw;
    const __half* Al = TWOPASS ? p.Al + (size_t)zq * p.sAz + (size_t)zr * p.sAw : nullptr;
    const __half* Bh = p.Bh + (size_t)zq * p.sBz + (size_t)zr * p.sBw;
    const size_t coff = (size_t)zq * p.sCz + (size_t)zr * p.sCw;
    const int rowBase = blockIdx.y * 64, colBase = blockIdx.x * 128;

    float acc[2][4][4];
#pragma unroll
    for (int i = 0; i < 2; i++)
#pragma unroll
        for (int j = 0; j < 4; j++)
#pragma unroll
            for (int q = 0; q < 4; q++) acc[i][j][q] = 0.f;

    const int nchunk = p.K >> 5;

    auto loadStage = [&](int s, int k0) {
        uint32_t base = sb + s * STAGE;
        load_a(base, Ah, p.lda, rowBase, k0, tid);
        if (TWOPASS) load_a(base + STG_A, Al, p.lda, rowBase, k0, tid);
        if (TRANSB) load_bt(base + 2 * STG_A, Bh, p.ldb, colBase, k0, tid);
        else        load_bn(base + 2 * STG_A, Bh, p.ldb, colBase, k0, tid);
        cpcommit();
    };

    loadStage(0, 0);
    for (int c = 0; c < nchunk; c++) {
        const int s = c & 1;
        if (c + 1 < nchunk) { loadStage(s ^ 1, (c + 1) << 5); cpwait<1>(); }
        else cpwait<0>();
        __syncthreads();

        const uint32_t base = sb + s * STAGE;
        const uint32_t aH = base, aL = base + STG_A;
        const uint32_t bH = base + 2 * STG_A;
#pragma unroll
        for (int kk = 0; kk < 2; kk++) {
            uint32_t ah[2][4], al[2][4], bh[4][2];
            const int ac = kk * 16 + (lane >> 4) * 8;
            const int ar = warpM * 32 + (lane & 15);
#pragma unroll
            for (int i = 0; i < 2; i++) {
                uint32_t off = (uint32_t)((ar + i * 16) * 48 + ac) * 2;
                ldsm4(ah[i], aH + off);
                if (TWOPASS) ldsm4(al[i], aL + off);
            }
            if (TRANSB) {
#pragma unroll
                for (int jj = 0; jj < 2; jj++) {
                    int br = warpN * 32 + jj * 16 + (lane & 15);
                    uint32_t off = (uint32_t)(br * 48 + ac) * 2;
                    uint32_t r[4];
                    ldsm4(r, bH + off);
                    bh[jj * 2][0] = r[0]; bh[jj * 2][1] = r[2];
                    bh[jj * 2 + 1][0] = r[1]; bh[jj * 2 + 1][1] = r[3];
                }
            } else {
#pragma unroll
                for (int jj = 0; jj < 2; jj++) {
                    int br = kk * 16 + (lane & 15);
                    int bc = warpN * 32 + jj * 16 + (lane >> 4) * 8;
                    uint32_t off = (uint32_t)(br * 136 + bc) * 2;
                    uint32_t r[4];
                    ldsm4t(r, bH + off);
                    bh[jj * 2][0] = r[0]; bh[jj * 2][1] = r[1];
                    bh[jj * 2 + 1][0] = r[2]; bh[jj * 2 + 1][1] = r[3];
                }
            }
#pragma unroll
            for (int i = 0; i < 2; i++)
#pragma unroll
                for (int j = 0; j < 4; j++) {
                    mma16816(acc[i][j], ah[i], bh[j]);
                    if (TWOPASS) mma16816(acc[i][j], al[i], bh[j]);
                }
        }
        __syncthreads();
    }

    // epilogue
    const float alpha = p.alpha;
#pragma unroll
    for (int i = 0; i < 2; i++) {
#pragma unroll
        for (int j = 0; j < 4; j++) {
            const int c0 = colBase + warpN * 32 + j * 8 + (lane & 3) * 2;
#pragma unroll
            for (int half = 0; half < 2; half++) {
                const int r = rowBase + warpM * 32 + i * 16 + (lane >> 2) + half * 8;
                float v0 = acc[i][j][half * 2] * alpha;
                float v1 = acc[i][j][half * 2 + 1] * alpha;
                if (p.bias) { v0 += p.bias[c0]; v1 += p.bias[c0 + 1]; }
                const size_t o = coff + (size_t)(r >> 11) * p.segA + p.segB
                               + (size_t)(r & 2047) * p.ldc + c0;
                if (p.add0) { v0 += p.add0[o]; v1 += p.add0[o + 1]; }
                if (p.gelu) {
                    v0 = 0.5f * v0 * (1.0f + erff(v0 * 0.70710678118654752440f));
                    v1 = 0.5f * v1 * (1.0f + erff(v1 * 0.70710678118654752440f));
                }
                if (p.outF) { float2 f2 = make_float2(v0, v1); *(float2*)(p.outF + o) = f2; }
                if (p.outHalf) {
                    __half2 hp; hp.x = __float2half(v0); hp.y = __float2half(v1);
                    *(__half2*)(p.outHalf + o) = hp;
                }
                if (p.outHi) {
                    __half h0 = __float2half(v0), h1 = __float2half(v1);
                    __half2 hh; hh.x = h0; hh.y = h1;
                    *(__half2*)(p.outHi + o) = hh;
                    if (p.outLo) {
                        __half2 ll;
                        ll.x = __float2half(v0 - __half2float(h0));
                        ll.y = __float2half(v1 - __half2float(h1));
                        *(__half2*)(p.outLo + o) = ll;
                    }
                }
            }
        }
    }
}

// ---------------- softmax + head-mean + adjacency ----------------
__device__ __forceinline__ float blockMax256(float v, float* red) {
#pragma unroll
    for (int o = 16; o; o >>= 1) v = fmaxf(v, __shfl_xor_sync(0xffffffffu, v, o));
    if ((threadIdx.x & 31) == 0) red[threadIdx.x >> 5] = v;
    __syncthreads();
    if (threadIdx.x < 32) {
        float x = (threadIdx.x < 8) ? red[threadIdx.x] : -3.4e38f;
#pragma unroll
        for (int o = 4; o; o >>= 1) x = fmaxf(x, __shfl_xor_sync(0xffffffffu, x, o));
        if (threadIdx.x == 0) red[0] = x;
    }
    __syncthreads();
    float r = red[0];
    __syncthreads();
    return r;
}
__device__ __forceinline__ float blockSum256(float v, float* red) {
#pragma unroll
    for (int o = 16; o; o >>= 1) v += __shfl_xor_sync(0xffffffffu, v, o);
    if ((threadIdx.x & 31) == 0) red[threadIdx.x >> 5] = v;
    __syncthreads();
    if (threadIdx.x < 32) {
        float x = (threadIdx.x < 8) ? red[threadIdx.x] : 0.f;
#pragma unroll
        for (int o = 4; o; o >>= 1) x += __shfl_xor_sync(0xffffffffu, x, o);
        if (threadIdx.x == 0) red[0] = x;
    }
    __syncthreads();
    float r = red[0];
    __syncthreads();
    return r;
}

// scores are fp16; reads/writes vectorized by pairs (j = 2*jp, 2*jp+1)
__global__ void __launch_bounds__(256) softmax_kernel() {
    const int i = blockIdx.x, b = blockIdx.y, tid = threadIdx.x;
    __shared__ float red[8];
    float wa[8];
#pragma unroll
    for (int u = 0; u < 8; u++) wa[u] = 0.f;
    for (int h = 0; h < CH; h++) {
        const __half2* row = (const __half2*)(g_scores + (((size_t)(b * CH + h) * CS) + i) * CS);
        float vals[8];
        float lmax = -3.4e38f;
#pragma unroll
        for (int u = 0; u < 4; u++) {
            __half2 pr = row[tid + 256 * u];
            float a0 = __half2float(pr.x), a1 = __half2float(pr.y);
            vals[2 * u] = a0; vals[2 * u + 1] = a1;
            lmax = fmaxf(lmax, fmaxf(a0, a1));
        }
        float m = blockMax256(lmax, red);
        float lsum = 0.f;
#pragma unroll
        for (int u = 0; u < 8; u++) { vals[u] = __expf(vals[u] - m); lsum += vals[u]; }
        float inv = 1.0f / blockSum256(lsum, red);
#pragma unroll
        for (int u = 0; u < 8; u++) wa[u] += vals[u] * inv;
    }
    float cnt = 0.f;
#pragma unroll
    for (int u = 0; u < 8; u++) {
        float wm = wa[u] * (1.0f / CH);
        wa[u] = wm;
        cnt += (wm > 0.1f) ? 1.f : 0.f;
    }
    float nn = fmaxf(blockSum256(cnt, red), 1.0f);
    float invn = 1.0f / nn;
    // combined A row: [wk(0..2047) | wm(2048..4095)], hi-only paired stores
    size_t base = ((size_t)b * CS + i) * (size_t)(2 * CS);
#pragma unroll
    for (int u = 0; u < 4; u++) {
        int jp = tid + 256 * u;
        float wm0 = wa[2 * u], wm1 = wa[2 * u + 1];
        float wk0 = (wm0 > 0.1f) ? wm0 * invn : 0.f;
        float wk1 = (wm1 > 0.1f) ? wm1 * invn : 0.f;
        __half2 hh;
        hh.x = __float2half(wk0); hh.y = __float2half(wk1);
        *(__half2*)(g_wh + base + 2 * jp) = hh;
        hh.x = __float2half(wm0); hh.y = __float2half(wm1);
        *(__half2*)(g_wh + base + 2048 + 2 * jp) = hh;
    }
}

// ---------------- fused prep kernel (xsplit + 6 weight converts + bm1eff) ----------------
constexpr int XBLK = (CBS * CE) / 256;          // 8192
constexpr int WBLK = (6 * CE * CE) / 256;       // 6144
__global__ void __launch_bounds__(256) prep_kernel(
    const float* __restrict__ x,
    const float* __restrict__ Wq, const float* __restrict__ Wk, const float* __restrict__ Wv,
    const float* __restrict__ Wm1, const float* __restrict__ Wm2, const float* __restrict__ Wo,
    const float* __restrict__ bm1) {
    const int bid = blockIdx.x, tid = threadIdx.x;
    if (bid < XBLK) {
        int idx = bid * 256 + tid;
        __half h = __float2half(x[idx]);
        g_xh[idx] = h;
        int b = idx >> 20;                 // CS*CE = 2^20
        int within = idx & ((CS * CE) - 1);
        g_xvh[(size_t)b * (2 * CS * CE) + within] = h;
    } else if (bid < XBLK + WBLK) {
        int widx = (bid - XBLK) * 256 + tid;
        int m = widx >> 18;                // / (CE*CE)
        int within = widx & (CE * CE - 1);
        int r = within >> 9, c = within & 511;
        const float* src;
        int ldin = CE;
        switch (m) {
            case 0: src = Wq; break;
            case 1: src = Wk; break;
            case 2: src = Wv; break;
            case 3: src = Wm1; ldin = CE + CH; break;
            case 4: src = Wm2; break;
            default: src = Wo; break;
        }
        g_Wh[widx] = __float2half(src[(size_t)r * ldin + c]);
    } else {
        int e = (bid - XBLK - WBLK) * 256 + tid;
        if (e < CE) {
            float s = 0.f;
#pragma unroll
            for (int c = 0; c < CH; c++) s += Wm1[(size_t)e * (CE + CH) + CE + c];
            g_bm1eff[e] = bm1[e] + s * (1.0f / CS);
        }
    }
}

// ---------------- host ----------------
static void run_mm(bool transb,
                   const __half* Ah, const __half* Al, int lda,
                   const __half* Bh, int ldb,
                   int M, int N, int K, float alpha,
                   const float* bias, const float* add0,
                   float* outF, __half* outHalf,
                   __half* outHi, __half* outLo,
                   int ldc, int gelu, int zcount, int zdiv,
                   long long sAz, long long sAw, long long sBz, long long sBw,
                   long long sCz, long long sCw,
                   long long segA = -1, long long segB = 0) {
    MP p;
    p.Ah = Ah; p.Al = Al; p.Bh = Bh;
    p.lda = lda; p.ldb = ldb; p.K = K; p.alpha = alpha;
    p.bias = bias; p.add0 = add0;
    p.outF = outF; p.outHalf = outHalf; p.outHi = outHi; p.outLo = outLo;
    p.ldc = ldc; p.gelu = gelu; p.zdiv = zdiv;
    p.sAz = sAz; p.sAw = sAw; p.sBz = sBz; p.sBw = sBw; p.sCz = sCz; p.sCw = sCw;
    p.segA = (segA < 0) ? (long long)2048 * ldc : segA;
    p.segB = segB;
    dim3 grid(N / 128, M / 64, zcount);
    const bool twopass = (Al != nullptr);
    if (transb) {
        if (twopass) mma_gemm<true, true><<<grid, 256, SMEM_BYTES>>>(p);
        else         mma_gemm<true, false><<<grid, 256, SMEM_BYTES>>>(p);
    } else {
        if (twopass) mma_gemm<false, true><<<grid, 256, SMEM_BYTES>>>(p);
        else         mma_gemm<false, false><<<grid, 256, SMEM_BYTES>>>(p);
    }
}

extern "C" void kernel_launch(void* const* d_in, const int* in_sizes, int n_in,
                              void* d_out, int out_size) {
    const float* x   = (const float*)d_in[0];
    const float* Wq  = (const float*)d_in[1];
    const float* bq  = (const float*)d_in[2];
    const float* Wk  = (const float*)d_in[3];
    const float* bk  = (const float*)d_in[4];
    const float* Wv  = (const float*)d_in[5];
    const float* bv  = (const float*)d_in[6];
    const float* Wm1 = (const float*)d_in[7];
    const float* bm1 = (const float*)d_in[8];
    const float* Wm2 = (const float*)d_in[9];
    const float* bm2 = (const float*)d_in[10];
    const float* Wo  = (const float*)d_in[11];
    const float* bo  = (const float*)d_in[12];
    float* out = (float*)d_out;

    cudaFuncSetAttribute(mma_gemm<true, true>,   cudaFuncAttributeMaxDynamicSharedMemorySize, SMEM_BYTES);
    cudaFuncSetAttribute(mma_gemm<true, false>,  cudaFuncAttributeMaxDynamicSharedMemorySize, SMEM_BYTES);
    cudaFuncSetAttribute(mma_gemm<false, true>,  cudaFuncAttributeMaxDynamicSharedMemorySize, SMEM_BYTES);
    cudaFuncSetAttribute(mma_gemm<false, false>, cudaFuncAttributeMaxDynamicSharedMemorySize, SMEM_BYTES);

    float *ma, *b1e;
    __half *sc, *xh, *qh, *kh, *xvh;
    __half *t1h, *t1l, *t2h, *t2l, *wh, *Wh;
    cudaGetSymbolAddress((void**)&sc, g_scores);
    cudaGetSymbolAddress((void**)&ma, g_msgatt);
    cudaGetSymbolAddress((void**)&b1e, g_bm1eff);
    cudaGetSymbolAddress((void**)&xh, g_xh);
    cudaGetSymbolAddress((void**)&qh, g_qh);
    cudaGetSymbolAddress((void**)&kh, g_kh);
    cudaGetSymbolAddress((void**)&xvh, g_xvh);
    cudaGetSymbolAddress((void**)&t1h, g_t1h); cudaGetSymbolAddress((void**)&t1l, g_t1l);
    cudaGetSymbolAddress((void**)&t2h, g_t2h); cudaGetSymbolAddress((void**)&t2l, g_t2l);
    cudaGetSymbolAddress((void**)&wh, g_wh);
    cudaGetSymbolAddress((void**)&Wh, g_Wh);

    const long long SE = (long long)CS * CE;
    const long long SS = (long long)CS * CS;
    const int WN = CE * CE;

    // fused prep: x hi, 6 weight converts, effective bm1
    prep_kernel<<<XBLK + WBLK + 2, 256>>>(x, Wq, Wk, Wv, Wm1, Wm2, Wo, bm1);

    // q, k (1-pass, hi only), v -> stacked [x;v] (1-pass, segment 1)
    run_mm(true, xh, nullptr, CE, Wh + 0 * WN, CE, CBS, CE, CE, 1.f, bq,
           nullptr, nullptr, nullptr, qh, nullptr, CE, 0, 1, 1, 0, 0, 0, 0, 0, 0);
    run_mm(true, xh, nullptr, CE, Wh + 1 * WN, CE, CBS, CE, CE, 1.f, bk,
           nullptr, nullptr, nullptr, kh, nullptr, CE, 0, 1, 1, 0, 0, 0, 0, 0, 0);
    run_mm(true, xh, nullptr, CE, Wh + 2 * WN, CE, CBS, CE, CE, 1.f, bv,
           nullptr, nullptr, nullptr, xvh, nullptr, CE, 0, 1, 1, 0, 0, 0, 0, 0, 0,
           (long long)2 * CS * CE /*segA: batch block*/, (long long)CS * CE /*segB: v segment*/);

    // scores (fp16) = 0.125 * q_h @ k_h^T  (z = b*8 + h) -- 1-pass
    run_mm(true, qh, nullptr, CE, kh, CE, CS, CS, 64, 0.125f, nullptr,
           nullptr, nullptr, sc, nullptr, nullptr, CS, 0,
           CB * CH, CH, SE, 64, SE, 64, (long long)CH * SS, SS);

    // softmax / adjacency -> combined [wk | wm] (hi only)
    {
        dim3 g(CS, CB);
        softmax_kernel<<<g, 256>>>();
    }

    // msg+att = [wk|wm] @ [x;v]   (K = 4096, per batch) -- 1-pass; outF = ma
    run_mm(false, wh, nullptr, 2 * CS, xvh, CE, CS, CE, 2 * CS, 1.f, nullptr,
           nullptr, ma, nullptr, nullptr, nullptr, CE, 0,
           CB, 1, (long long)CS * 2 * CS, 0, (long long)2 * CS * CE, 0, SE, 0);

    // t1 = gelu(x @ Wm1'^T + bm1eff)  -- 1-pass A, output hi+lo
    run_mm(true, xh, nullptr, CE, Wh + 3 * WN, CE, CBS, CE, CE, 1.f, b1e,
           nullptr, nullptr, nullptr, t1h, t1l, CE, 1, 1, 1, 0, 0, 0, 0, 0, 0);

    // t2 = t1 @ Wm2^T + bm2 + (msg+att)  (2-pass A=t1)
    run_mm(true, t1h, t1l, CE, Wh + 4 * WN, CE, CBS, CE, CE, 1.f, bm2,
           ma, nullptr, nullptr, t2h, t2l, CE, 0, 1, 1, 0, 0, 0, 0, 0, 0);

    // out = t2 @ Wo^T + bo  (2-pass A=t2); outF = out
    run_mm(true, t2h, t2l, CE, Wh + 5 * WN, CE, CBS, CE, CE, 1.f, bo,
           nullptr, out, nullptr, nullptr, nullptr, CE, 0, 1, 1, 0, 0, 0, 0, 0, 0);
}